// round 12
// baseline (speedup 1.0000x reference)
#include <cuda_runtime.h>
#include <cuda_fp16.h>
#include <math.h>
#include <stdint.h>

// Problem constants
constexpr int Bc  = 4;
constexpr int Lc  = 1024;
constexpr int Dc  = 1024;
constexpr int Fc  = 4096;
constexpr int HDc = 64;
constexpr int BLc = Bc * Lc;          // 4096 rows
constexpr int QKVW = 3 * Dc;          // 3072 concat width

// ---------------------------------------------------------------------------
// Scratch (static __device__ arrays — allocation-free per harness rules)
// ---------------------------------------------------------------------------
__device__ float g_Mo0[BLc * Dc];
__device__ float g_Mo1[BLc * Dc];
__device__ float g_T1f[BLc * Dc];
__device__ float g_A1f[BLc * Dc];

__device__ __half g_iT [BLc*Dc], g_iA [BLc*Dc];
__device__ __half g_T1 [BLc*Dc], g_A1 [BLc*Dc];
__device__ __half g_T2 [BLc*Dc], g_A2 [BLc*Dc];
__device__ __half g_O0 [BLc*Dc], g_O1 [BLc*Dc];
__device__ __half g_H0 [(size_t)BLc*Fc], g_H1 [(size_t)BLc*Fc];
__device__ __half g_QKV0[(size_t)BLc*QKVW];
__device__ __half g_QKV1[(size_t)BLc*QKVW];

// weights: single fp16, concat QKV^T [4][3072,1024]; others [N,K]
__device__ __half g_wc[(size_t)4*QKVW*Dc];
__device__ __half g_wo[4*Dc*Dc];
__device__ __half g_w1[2*Dc*Fc];
__device__ __half g_w2[2*Fc*Dc];
__device__ float g_bcat[4*QKVW];

// ---------------------------------------------------------------------------
// PTX helpers (sm_103 baseline-safe)
// ---------------------------------------------------------------------------
__device__ __forceinline__ uint32_t smem_u32(const void* p) {
    uint32_t a;
    asm("{ .reg .u64 t; cvta.to.shared.u64 t, %1; cvt.u32.u64 %0, t; }" : "=r"(a) : "l"(p));
    return a;
}
__device__ __forceinline__ void cpasync16(uint32_t dst, const void* src) {
    asm volatile("cp.async.cg.shared.global [%0], [%1], 16;" :: "r"(dst), "l"(src));
}
#define CP_COMMIT()  asm volatile("cp.async.commit_group;" ::: "memory")
#define CP_WAIT(n)   asm volatile("cp.async.wait_group %0;" :: "n"(n) : "memory")

#define LDSM4(r, a) \
    asm volatile("ldmatrix.sync.aligned.m8n8.x4.shared.b16 {%0,%1,%2,%3}, [%4];" \
        : "=r"((r)[0]), "=r"((r)[1]), "=r"((r)[2]), "=r"((r)[3]) : "r"(a))
#define LDSM4T(r, a) \
    asm volatile("ldmatrix.sync.aligned.m8n8.x4.trans.shared.b16 {%0,%1,%2,%3}, [%4];" \
        : "=r"((r)[0]), "=r"((r)[1]), "=r"((r)[2]), "=r"((r)[3]) : "r"(a))

__device__ __forceinline__ void mma16816(float* c, const uint32_t* a, const uint32_t* b) {
    asm volatile(
        "mma.sync.aligned.m16n8k16.row.col.f32.f16.f16.f32 "
        "{%0,%1,%2,%3}, {%4,%5,%6,%7}, {%8,%9}, {%0,%1,%2,%3};"
        : "+f"(c[0]), "+f"(c[1]), "+f"(c[2]), "+f"(c[3])
        : "r"(a[0]), "r"(a[1]), "r"(a[2]), "r"(a[3]), "r"(b[0]), "r"(b[1]));
}

__device__ __forceinline__ uint32_t packh(float a, float b) {
    __half2 t; t.x = __float2half(a); t.y = __float2half(b);
    return *(uint32_t*)&t;
}
#define FSW(o) ((o) ^ (((o) >> 3) & 0x70))     // SW128 swizzle for 128B rows

// ---------------------------------------------------------------------------
// Tensor-core GEMM, templated tile height BM (128: 256thr/occ2; 256: 512thr/occ1).
// C[M,N] = A[M,K] @ B[N,K]^T (+bias)(+resid)(+relu); single fp16, fp32 acc;
// 3-stage cp.async. Output fp32 (C) and/or fp16 (Ch). ldc stride, coff offset.
// ---------------------------------------------------------------------------
template<int BM, int NT>
__global__ __launch_bounds__(NT, (BM == 128) ? 2 : 1) void gemm_mma(
    const __half* __restrict__ Aa, const __half* __restrict__ Bb,
    const float* __restrict__ bias, const float* __restrict__ resid,
    float* __restrict__ C, __half* __restrict__ Ch,
    int M, int N, int K, int ldc, int coff, int relu)
{
    constexpr int STAGE_B = (BM + 128) * 80;
    extern __shared__ char sm[];
    const uint32_t sb = smem_u32(sm);
    const int tid  = threadIdx.x;
    const int wid  = tid >> 5;
    const int lane = tid & 31;
    const int brow = blockIdx.y * BM;
    const int bcol = blockIdx.x * 128;
    const int wm   = (wid % (BM / 64)) * 64;
    const int wn   = (wid / (BM / 64)) * 32;

    float acc[4][4][4];
    #pragma unroll
    for (int i = 0; i < 4; i++)
        #pragma unroll
        for (int j = 0; j < 4; j++)
            #pragma unroll
            for (int k = 0; k < 4; k++) acc[i][j][k] = 0.f;

    const int nch = K >> 5;

    auto issue = [&](int c, int s) {
        const int kc = c << 5;
        const uint32_t st = sb + s * STAGE_B;
        #pragma unroll
        for (int i = tid; i < (BM + 128) * 4; i += NT) {
            const int r = i >> 2, q = i & 3;
            const uint32_t so = (uint32_t)(r * 80 + q * 16);
            if (r < BM)
                cpasync16(st + so, Aa + (size_t)(brow + r) * K + kc + q * 8);
            else
                cpasync16(st + so, Bb + (size_t)(bcol + r - BM) * K + kc + q * 8);
        }
        CP_COMMIT();
    };

    issue(0, 0);
    if (nch > 1) issue(1, 1);

    const int a_row = (lane & 15);
    const int a_kof = ((lane >> 4) << 3);
    const int g8    = lane >> 3;
    const int b_nt  = (g8 >> 1) << 3;
    const int b_kof = (g8 & 1) << 3;
    const int b_row = (lane & 7);

    for (int c = 0; c < nch; c++) {
        if (c + 2 < nch) { issue(c + 2, (c + 2) % 3); CP_WAIT(2); }
        else if (c + 1 < nch) CP_WAIT(1);
        else CP_WAIT(0);
        __syncthreads();

        const uint32_t st = sb + (c % 3) * STAGE_B;
        #pragma unroll
        for (int k16 = 0; k16 < 32; k16 += 16) {
            uint32_t aH[4][4], t[4];
            #pragma unroll
            for (int mt = 0; mt < 4; mt++) {
                uint32_t ad = st + (uint32_t)((wm + mt*16 + a_row) * 80
                                              + (k16 + a_kof) * 2);
                LDSM4(aH[mt], ad);
            }
            #pragma unroll
            for (int p = 0; p < 2; p++) {
                uint32_t ad = st + (uint32_t)(BM * 80)
                    + (uint32_t)((wn + p*16 + b_nt + b_row) * 80
                                 + (k16 + b_kof) * 2);
                LDSM4(t, ad);
                uint32_t b0[2] = { t[0], t[1] }, b1[2] = { t[2], t[3] };
                #pragma unroll
                for (int mt = 0; mt < 4; mt++) {
                    mma16816(acc[mt][2*p    ], aH[mt], b0);
                    mma16816(acc[mt][2*p + 1], aH[mt], b1);
                }
            }
        }
        __syncthreads();
    }

    const int g  = lane >> 2;
    const int tg = lane & 3;
    #pragma unroll
    for (int mt = 0; mt < 4; mt++) {
        #pragma unroll
        for (int nt = 0; nt < 4; nt++) {
            const int row = brow + wm + mt*16 + g;
            const int col = bcol + wn + nt*8 + tg*2;
            float2 v0, v1;
            v0.x = acc[mt][nt][0]; v0.y = acc[mt][nt][1];
            v1.x = acc[mt][nt][2]; v1.y = acc[mt][nt][3];
            if (bias) {
                float2 bb = *(const float2*)&bias[col];
                v0.x += bb.x; v0.y += bb.y; v1.x += bb.x; v1.y += bb.y;
            }
            const size_t o0 = (size_t)row * ldc + coff + col;
            const size_t o1 = (size_t)(row + 8) * ldc + coff + col;
            if (resid) {
                float2 r0 = *(const float2*)&resid[o0];
                float2 r1 = *(const float2*)&resid[o1];
                v0.x += r0.x; v0.y += r0.y; v1.x += r1.x; v1.y += r1.y;
            }
            if (relu) {
                v0.x = fmaxf(v0.x, 0.f); v0.y = fmaxf(v0.y, 0.f);
                v1.x = fmaxf(v1.x, 0.f); v1.y = fmaxf(v1.y, 0.f);
            }
            if (C) {
                *(float2*)&C[o0] = v0;
                *(float2*)&C[o1] = v1;
            }
            if (Ch) {
                *(uint32_t*)&Ch[o0] = packh(v0.x, v0.y);
                *(uint32_t*)&Ch[o1] = packh(v1.x, v1.y);
            }
        }
    }
}

// ---------------------------------------------------------------------------
// Fused flash attention: single fp16, fp32 acc, occ 2, 3-stage KV pipeline.
// ---------------------------------------------------------------------------
constexpr int FA_QTB   = 128 * 144;               // 18432 B
constexpr int FA_KTB   = 64 * 128;                // 8192 B
constexpr int FA_STAGE = 2 * FA_KTB;              // K,V = 16384 B
constexpr int FA_SMEM  = FA_QTB + 3*FA_STAGE + 4096;   // 71680 B

__global__ __launch_bounds__(256, 2) void flash_attn(
    const __half* __restrict__ X,
    const float* __restrict__ mask, const int* __restrict__ pad,
    __half* __restrict__ O)
{
    extern __shared__ char sm[];
    const uint32_t sb = smem_u32(sm);
    const int tid  = threadIdx.x;
    const int wid  = tid >> 5;
    const int lane = tid & 31;
    const int qy   = blockIdx.x * 128;
    const int bh   = blockIdx.y;
    const int b    = bh >> 4;
    const int hcol = (bh & 15) * HDc;
    const int wq   = wid * 16;

    const uint32_t sQ     = sb;
    const uint32_t sStage = sb + FA_QTB;
    float* spad = (float*)(sm + FA_QTB + 3*FA_STAGE);

    for (int i = tid; i < 1024; i += 256)
        spad[i] = (float)pad[b*Lc + i];

    for (int i = tid; i < 1024; i += 256) {
        const int r = i >> 3, j = i & 7;
        const uint32_t so = (uint32_t)(r * 144 + j * 16);
        cpasync16(sQ + so, X + (size_t)(b*Lc + qy + r) * QKVW + hcol + j*8);
    }
    CP_COMMIT();

    auto issueKV = [&](int t, int s) {
        const int kx = t * 64;
        const uint32_t base = sStage + s * FA_STAGE;
        for (int i = tid; i < 512; i += 256) {
            const int r = i >> 3, j = i & 7;
            const uint32_t so = FSW((uint32_t)(r * 128 + j * 16));
            const size_t gk = (size_t)(b*Lc + kx + r) * QKVW + 1024 + hcol + j*8;
            cpasync16(base + so,            X + gk);
            cpasync16(base + FA_KTB + so,   X + gk + 1024);
        }
        CP_COMMIT();
    };
    issueKV(0, 0);
    issueKV(1, 1);

    CP_WAIT(2);          // Q complete (2 KV groups may remain outstanding)
    __syncthreads();

    const int a_row = lane & 15;
    const int a_kof = (lane >> 4) << 3;
    uint32_t qh[4][4];
    #pragma unroll
    for (int kt = 0; kt < 4; kt++)
        LDSM4(qh[kt], sQ + (uint32_t)((wq + a_row)*144 + (kt*16 + a_kof)*2));

    float m[2] = { -1e30f, -1e30f };
    float l[2] = { 0.f, 0.f };
    float o[8][4];
    #pragma unroll
    for (int i = 0; i < 8; i++)
        #pragma unroll
        for (int j = 0; j < 4; j++) o[i][j] = 0.f;

    const int g    = lane >> 2;
    const int tg   = lane & 3;
    const int g8   = lane >> 3;
    const int b_nt  = (g8 >> 1) << 3;
    const int b_kof = (g8 & 1) << 3;
    const int b_row = lane & 7;
    const int v_kv = ((lane >> 3) & 1) << 3;
    const int v_d  = (lane >> 4) << 3;

    for (int t = 0; t < 16; t++) {
        const int kx = t * 64;
        if (t + 2 < 16) { issueKV(t + 2, (t + 2) % 3); CP_WAIT(2); }
        else if (t + 1 < 16) CP_WAIT(1);
        else CP_WAIT(0);
        __syncthreads();

        const uint32_t stK = sStage + (t % 3) * FA_STAGE;
        const uint32_t stV = stK + FA_KTB;

        float sf[8][4];
        #pragma unroll
        for (int i = 0; i < 8; i++)
            #pragma unroll
            for (int j = 0; j < 4; j++) sf[i][j] = 0.f;

        #pragma unroll
        for (int kst = 0; kst < 4; kst++) {
            uint32_t kb[4][4];
            #pragma unroll
            for (int p = 0; p < 4; p++) {
                const uint32_t ad = stK + FSW((uint32_t)((p*16 + b_nt + b_row)*128
                                                          + kst*32 + b_kof*2));
                LDSM4(kb[p], ad);
            }
            #pragma unroll
            for (int p = 0; p < 4; p++) {
                uint32_t b0[2] = { kb[p][0], kb[p][1] };
                uint32_t b1[2] = { kb[p][2], kb[p][3] };
                mma16816(sf[2*p],   qh[kst], b0);
                mma16816(sf[2*p+1], qh[kst], b1);
            }
        }

        const int qg0 = qy + wq + g;
        #pragma unroll
        for (int nt = 0; nt < 8; nt++) {
            const int kvl = nt*8 + tg*2;
            const int kvg = kx + kvl;
            float2 m0 = *(const float2*)&mask[(size_t)qg0 * Lc + kvg];
            float2 m1 = *(const float2*)&mask[(size_t)(qg0 + 8) * Lc + kvg];
            const float p0 = spad[kvg], p1 = spad[kvg + 1];
            sf[nt][0] = sf[nt][0]*0.125f + m0.x + p0;
            sf[nt][1] = sf[nt][1]*0.125f + m0.y + p1;
            sf[nt][2] = sf[nt][2]*0.125f + m1.x + p0;
            sf[nt][3] = sf[nt][3]*0.125f + m1.y + p1;
        }

        float mx0 = m[0], mx1 = m[1];
        #pragma unroll
        for (int nt = 0; nt < 8; nt++) {
            mx0 = fmaxf(mx0, fmaxf(sf[nt][0], sf[nt][1]));
            mx1 = fmaxf(mx1, fmaxf(sf[nt][2], sf[nt][3]));
        }
        mx0 = fmaxf(mx0, __shfl_xor_sync(0xffffffffu, mx0, 1));
        mx0 = fmaxf(mx0, __shfl_xor_sync(0xffffffffu, mx0, 2));
        mx1 = fmaxf(mx1, __shfl_xor_sync(0xffffffffu, mx1, 1));
        mx1 = fmaxf(mx1, __shfl_xor_sync(0xffffffffu, mx1, 2));

        const float al0 = __expf(m[0] - mx0);
        const float al1 = __expf(m[1] - mx1);
        m[0] = mx0; m[1] = mx1;
        #pragma unroll
        for (int nt = 0; nt < 8; nt++) {
            o[nt][0] *= al0; o[nt][1] *= al0;
            o[nt][2] *= al1; o[nt][3] *= al1;
        }

        uint32_t ph[4][4];
        float s0 = 0.f, s1 = 0.f;
        #pragma unroll
        for (int j = 0; j < 4; j++) {
            float e00 = __expf(sf[2*j][0]   - mx0);
            float e01 = __expf(sf[2*j][1]   - mx0);
            float e10 = __expf(sf[2*j][2]   - mx1);
            float e11 = __expf(sf[2*j][3]   - mx1);
            float e20 = __expf(sf[2*j+1][0] - mx0);
            float e21 = __expf(sf[2*j+1][1] - mx0);
            float e30 = __expf(sf[2*j+1][2] - mx1);
            float e31 = __expf(sf[2*j+1][3] - mx1);
            s0 += e00 + e01 + e20 + e21;
            s1 += e10 + e11 + e30 + e31;
            ph[j][0] = packh(e00, e01);
            ph[j][1] = packh(e10, e11);
            ph[j][2] = packh(e20, e21);
            ph[j][3] = packh(e30, e31);
        }
        s0 += __shfl_xor_sync(0xffffffffu, s0, 1);
        s0 += __shfl_xor_sync(0xffffffffu, s0, 2);
        s1 += __shfl_xor_sync(0xffffffffu, s1, 1);
        s1 += __shfl_xor_sync(0xffffffffu, s1, 2);
        l[0] = l[0]*al0 + s0;
        l[1] = l[1]*al1 + s1;

        #pragma unroll
        for (int j = 0; j < 4; j++) {
            #pragma unroll
            for (int p = 0; p < 4; p++) {
                uint32_t th[4];
                const uint32_t off = FSW((uint32_t)((j*16 + v_kv + b_row)*128
                                                     + p*32 + v_d*2));
                LDSM4T(th, stV + off);
                uint32_t b0[2] = { th[0], th[1] }, b1[2] = { th[2], th[3] };
                mma16816(o[2*p],   ph[j], b0);
                mma16816(o[2*p+1], ph[j], b1);
            }
        }
        __syncthreads();
    }

    const float inv0 = 1.f / l[0];
    const float inv1 = 1.f / l[1];
    const int row = b*Lc + qy + wq + g;
    #pragma unroll
    for (int nt = 0; nt < 8; nt++) {
        const int col = hcol + nt*8 + tg*2;
        *(uint32_t*)&O[(size_t)row * Dc + col]       = packh(o[nt][0]*inv0, o[nt][1]*inv0);
        *(uint32_t*)&O[(size_t)(row + 8) * Dc + col] = packh(o[nt][2]*inv1, o[nt][3]*inv1);
    }
}

// ---------------------------------------------------------------------------
// small kernels
// ---------------------------------------------------------------------------
__global__ __launch_bounds__(256) void cvt_f16(
    const float* __restrict__ x, __half* __restrict__ h)
{
    const size_t i = ((size_t)blockIdx.x * 256 + threadIdx.x) * 4;
    float4 v = *(const float4*)(x + i);
    *(uint32_t*)(h + i)     = packh(v.x, v.y);
    *(uint32_t*)(h + i + 2) = packh(v.z, v.w);
}

__global__ __launch_bounds__(256) void transpose_cvt(
    const float* __restrict__ W, __half* __restrict__ h,
    int K, int N, size_t ostrideZ)
{
    __shared__ float t[32][33];
    const size_t ibase = (size_t)blockIdx.z * K * N;
    const size_t obase = (size_t)blockIdx.z * ostrideZ;
    const int k0 = blockIdx.y * 32, n0 = blockIdx.x * 32;
    const int tx = threadIdx.x & 31, ty = threadIdx.x >> 5;
    #pragma unroll
    for (int r = 0; r < 32; r += 8)
        t[ty + r][tx] = W[ibase + (size_t)(k0 + ty + r) * N + n0 + tx];
    __syncthreads();
    #pragma unroll
    for (int r = 0; r < 32; r += 8) {
        const size_t o = obase + (size_t)(n0 + ty + r) * K + k0 + tx;
        h[o] = __float2half(t[tx][ty + r]);
    }
}

__global__ void bias_cat(const float* __restrict__ bq, const float* __restrict__ bk,
                         const float* __restrict__ bv, float* __restrict__ o)
{
    const int i = blockIdx.x, seg = blockIdx.y, j = threadIdx.x;
    const float* src = (seg == 0) ? bq : (seg == 1) ? bk : bv;
    o[i*QKVW + seg*1024 + j] = src[i*1024 + j];
}

// LN over rows (res nullable: x may already hold the residual sum)
__global__ __launch_bounds__(256) void add_ln(
    const float* __restrict__ x, const float* __restrict__ res,
    const float* __restrict__ g, const float* __restrict__ bta,
    float* __restrict__ y, __half* __restrict__ yh)
{
    __shared__ float rs[8], rq[8];
    const int tid = threadIdx.x;
    const size_t base = (size_t)blockIdx.x * 1024 + tid * 4;

    float4 a = *(const float4*)&x[base];
    if (res) {
        float4 r = *(const float4*)&res[base];
        a.x += r.x; a.y += r.y; a.z += r.z; a.w += r.w;
    }

    float s = a.x + a.y + a.z + a.w;
    float q = a.x*a.x + a.y*a.y + a.z*a.z + a.w*a.w;
    #pragma unroll
    for (int o = 16; o > 0; o >>= 1) {
        s += __shfl_xor_sync(0xffffffffu, s, o);
        q += __shfl_xor_sync(0xffffffffu, q, o);
    }
    if ((tid & 31) == 0) { rs[tid >> 5] = s; rq[tid >> 5] = q; }
    __syncthreads();
    s = 0.f; q = 0.f;
    #pragma unroll
    for (int i = 0; i < 8; i++) { s += rs[i]; q += rq[i]; }

    const float mean = s * (1.f / 1024.f);
    const float var  = q * (1.f / 1024.f) - mean * mean;
    const float rstd = rsqrtf(var + 1e-5f);

    const int c = tid * 4;
    float4 gv = *(const float4*)&g[c];
    float4 bv = *(const float4*)&bta[c];
    float4 o;
    o.x = (a.x - mean) * rstd * gv.x + bv.x;
    o.y = (a.y - mean) * rstd * gv.y + bv.y;
    o.z = (a.z - mean) * rstd * gv.z + bv.z;
    o.w = (a.w - mean) * rstd * gv.w + bv.w;
    if (y) *(float4*)&y[base] = o;

    *(uint32_t*)&yh[base]     = packh(o.x, o.y);
    *(uint32_t*)&yh[base + 2] = packh(o.z, o.w);
}

// ---------------------------------------------------------------------------
// Launch orchestration — round 9 DAG; BM256 for big GEMMs; residual-fused Wo
// ---------------------------------------------------------------------------
extern "C" void kernel_launch(void* const* d_in, const int* in_sizes, int n_in,
                              void* d_out, int out_size)
{
    const float* T    = (const float*)d_in[0];
    const float* A    = (const float*)d_in[1];
    const float* mask = (const float*)d_in[2];
    const int*   pad  = (const int*)  d_in[3];
    const float* Wq   = (const float*)d_in[4];
    const float* bq   = (const float*)d_in[5];
    const float* Wk   = (const float*)d_in[6];
    const float* bk   = (const float*)d_in[7];
    const float* Wv   = (const float*)d_in[8];
    const float* bv   = (const float*)d_in[9];
    const float* Wo   = (const float*)d_in[10];
    const float* ffW1 = (const float*)d_in[11];
    const float* ffb1 = (const float*)d_in[12];
    const float* ffW2 = (const float*)d_in[13];
    const float* ffb2 = (const float*)d_in[14];
    const float* lng  = (const float*)d_in[15];
    const float* lnb  = (const float*)d_in[16];
    float* out = (float*)d_out;

    static cudaStream_t sA = nullptr, sB = nullptr, sC = nullptr;
    static cudaEvent_t  eF = nullptr, eA = nullptr, eB = nullptr;
    static cudaEvent_t  eC = nullptr, eQ2 = nullptr, eKV2 = nullptr, eQ3 = nullptr;
    if (!sA) {
        cudaStreamCreateWithFlags(&sA, cudaStreamNonBlocking);
        cudaStreamCreateWithFlags(&sB, cudaStreamNonBlocking);
        cudaStreamCreateWithFlags(&sC, cudaStreamNonBlocking);
        cudaEventCreateWithFlags(&eF,  cudaEventDisableTiming);
        cudaEventCreateWithFlags(&eA,  cudaEventDisableTiming);
        cudaEventCreateWithFlags(&eB,  cudaEventDisableTiming);
        cudaEventCreateWithFlags(&eC,  cudaEventDisableTiming);
        cudaEventCreateWithFlags(&eQ2, cudaEventDisableTiming);
        cudaEventCreateWithFlags(&eKV2,cudaEventDisableTiming);
        cudaEventCreateWithFlags(&eQ3, cudaEventDisableTiming);
    }
    auto fork = [&]() {
        cudaEventRecord(eF, 0);
        cudaStreamWaitEvent(sA, eF, 0);
        cudaStreamWaitEvent(sB, eF, 0);
    };
    auto join = [&]() {
        cudaEventRecord(eA, sA);
        cudaEventRecord(eB, sB);
        cudaStreamWaitEvent(0, eA, 0);
        cudaStreamWaitEvent(0, eB, 0);
    };

    float *Mo0, *Mo1, *T1f, *A1f;
    cudaGetSymbolAddress((void**)&Mo0, g_Mo0);
    cudaGetSymbolAddress((void**)&Mo1, g_Mo1);
    cudaGetSymbolAddress((void**)&T1f, g_T1f);
    cudaGetSymbolAddress((void**)&A1f, g_A1f);

    __half *iT,*iA,*T1,*A1,*T2,*A2,*O0,*O1,*H0,*H1,*QKV0,*QKV1;
    __half *wc,*wo,*w1,*w2;
    float* bcat;
    cudaGetSymbolAddress((void**)&iT, g_iT);   cudaGetSymbolAddress((void**)&iA, g_iA);
    cudaGetSymbolAddress((void**)&T1, g_T1);   cudaGetSymbolAddress((void**)&A1, g_A1);
    cudaGetSymbolAddress((void**)&T2, g_T2);   cudaGetSymbolAddress((void**)&A2, g_A2);
    cudaGetSymbolAddress((void**)&O0, g_O0);   cudaGetSymbolAddress((void**)&O1, g_O1);
    cudaGetSymbolAddress((void**)&H0, g_H0);   cudaGetSymbolAddress((void**)&H1, g_H1);
    cudaGetSymbolAddress((void**)&QKV0, g_QKV0);
    cudaGetSymbolAddress((void**)&QKV1, g_QKV1);
    cudaGetSymbolAddress((void**)&wc, g_wc);   cudaGetSymbolAddress((void**)&wo, g_wo);
    cudaGetSymbolAddress((void**)&w1, g_w1);   cudaGetSymbolAddress((void**)&w2, g_w2);
    cudaGetSymbolAddress((void**)&bcat, g_bcat);

    constexpr int SM128 = (128 + 128) * 80 * 3;    // 61440
    constexpr int SM256 = (256 + 128) * 80 * 3;    // 92160
    cudaFuncSetAttribute(gemm_mma<128,256>, cudaFuncAttributeMaxDynamicSharedMemorySize, SM128);
    cudaFuncSetAttribute(gemm_mma<256,512>, cudaFuncAttributeMaxDynamicSharedMemorySize, SM256);
    cudaFuncSetAttribute(flash_attn, cudaFuncAttributeMaxDynamicSharedMemorySize, FA_SMEM);

    const size_t DD = (size_t)Dc * Dc;
    const size_t WCZ = (size_t)QKVW * Dc;

    auto g128 = [&](cudaStream_t st, const __half* a, const __half* b,
                    const float* bias, const float* resid, float* c, __half* ch,
                    int M, int N, int K, int ldc, int coff, int relu) {
        gemm_mma<128,256><<<dim3(N/128, M/128), 256, SM128, st>>>(
            a, b, bias, resid, c, ch, M, N, K, ldc, coff, relu);
    };
    auto g256 = [&](cudaStream_t st, const __half* a, const __half* b,
                    const float* bias, const float* resid, float* c, __half* ch,
                    int M, int N, int K, int ldc, int coff, int relu) {
        gemm_mma<256,512><<<dim3(N/128, M/256), 512, SM256, st>>>(
            a, b, bias, resid, c, ch, M, N, K, ldc, coff, relu);
    };

    // ------- Phase 0: CRITICAL prep (sA/sB) + DEFERRED prep (sC) -------
    fork();
    cudaStreamWaitEvent(sC, eF, 0);
    transpose_cvt<<<dim3(32,32,2), 256, 0, sA>>>(Wq, wc,        Dc, Dc, WCZ);
    transpose_cvt<<<dim3(32,32,2), 256, 0, sA>>>(Wk, wc + DD,   Dc, Dc, WCZ);
    transpose_cvt<<<dim3(32,32,2), 256, 0, sA>>>(Wv, wc + 2*DD, Dc, Dc, WCZ);
    bias_cat<<<dim3(4,3), 1024, 0, sA>>>(bq, bk, bv, bcat);
    cvt_f16<<<BLc, 256, 0, sA>>>(T, iT);
    transpose_cvt<<<dim3(32,32,2), 256, 0, sB>>>(Wo, wo, Dc, Dc, DD);
    cvt_f16<<<BLc, 256, 0, sB>>>(A, iA);
    transpose_cvt<<<dim3(32,32,2), 256, 0, sC>>>(Wq + 2*DD, wc + 2*WCZ,        Dc, Dc, WCZ);
    transpose_cvt<<<dim3(32,32,2), 256, 0, sC>>>(Wk + 2*DD, wc + 2*WCZ + DD,   Dc, Dc, WCZ);
    transpose_cvt<<<dim3(32,32,2), 256, 0, sC>>>(Wv + 2*DD, wc + 2*WCZ + 2*DD, Dc, Dc, WCZ);
    transpose_cvt<<<dim3(32,32,2), 256, 0, sC>>>(Wo + 2*DD, wo + 2*DD, Dc, Dc, DD);
    transpose_cvt<<<dim3(128,32,2), 256, 0, sC>>>(ffW1, w1, Dc, Fc, (size_t)Dc*Fc);
    transpose_cvt<<<dim3(32,128,2), 256, 0, sC>>>(ffW2, w2, Fc, Dc, (size_t)Fc*Dc);
    cudaEventRecord(eC, sC);
    join();

    // ---------------- Phase 1: mha0 (T, sA) || mha1 (A, sB) ----------------
    fork();
    g256(sA, iT, wc, bcat, nullptr, nullptr, QKV0, BLc, QKVW, Dc, QKVW, 0, 0);
    flash_attn<<<dim3(Lc/128, 64), 256, FA_SMEM, sA>>>(QKV0, mask, pad, O0);
    g128(sA, O0, wo, nullptr, T, Mo0, nullptr, BLc, Dc, Dc, Dc, 0, 0);    // Mo0 = O0@Wo + T
    add_ln<<<BLc, 256, 0, sA>>>(Mo0, nullptr, lng, lnb, T1f, T1);
    g256(sB, iA, wc + WCZ, bcat + QKVW, nullptr, nullptr, QKV1, BLc, QKVW, Dc, QKVW, 0, 0);
    flash_attn<<<dim3(Lc/128, 64), 256, FA_SMEM, sB>>>(QKV1, mask, pad, O1);
    g128(sB, O1, wo + DD, nullptr, A, Mo1, nullptr, BLc, Dc, Dc, Dc, 0, 0);
    add_ln<<<BLc, 256, 0, sB>>>(Mo1, nullptr, lng + Dc, lnb + Dc, A1f, A1);
    join();
    cudaStreamWaitEvent(0, eC, 0);

    // ------- Phase 2: KV2 (sA) || Q2,Q3 (sB); flash2 waits only {KV2,Q2} -------
    fork();
    g128(sA, A1, wc + 2*WCZ + DD, bcat + 2*QKVW + 1024, nullptr,
         nullptr, QKV0, BLc, 2*Dc, Dc, QKVW, 1024, 0);
    cudaEventRecord(eKV2, sA);
    g128(sB, T1, wc + 2*WCZ, bcat + 2*QKVW, nullptr, nullptr, QKV0,
         BLc, Dc, Dc, QKVW, 0, 0);
    cudaEventRecord(eQ2, sB);
    g128(sB, A1, wc + 3*WCZ, bcat + 3*QKVW, nullptr, nullptr, QKV1,
         BLc, Dc, Dc, QKVW, 0, 0);
    cudaEventRecord(eQ3, sB);

    cudaStreamWaitEvent(0, eKV2, 0);
    cudaStreamWaitEvent(0, eQ2, 0);
    flash_attn<<<dim3(Lc/128, 64), 256, FA_SMEM>>>(QKV0, mask, pad, O0);
    g128(0, O0, wo + 2*DD, nullptr, T1f, Mo0, nullptr, BLc, Dc, Dc, Dc, 0, 0);
    add_ln<<<BLc, 256>>>(Mo0, nullptr, lng + 2*Dc, lnb + 2*Dc, nullptr, T2);

    // ------- Phase 3: mha3 chain + FFN-A (sA)  ||  FFN-T (sB) -------
    fork();
    g128(sA, T2, wc + 3*WCZ + DD, bcat + 3*QKVW + 1024, nullptr,
         nullptr, QKV1, BLc, 2*Dc, Dc, QKVW, 1024, 0);
    cudaStreamWaitEvent(sA, eQ3, 0);
    flash_attn<<<dim3(Lc/128, 64), 256, FA_SMEM, sA>>>(QKV1, mask, pad, O0);
    g128(sA, O0, wo + 3*DD, nullptr, A1f, Mo0, nullptr, BLc, Dc, Dc, Dc, 0, 0);
    add_ln<<<BLc, 256, 0, sA>>>(Mo0, nullptr, lng + 3*Dc, lnb + 3*Dc, nullptr, A2);
    g256(sA, A2, w1 + (size_t)Dc*Fc, ffb1 + Fc, nullptr, nullptr, H1,
         BLc, Fc, Dc, Fc, 0, 1);
    g128(sA, H1, w2 + (size_t)Fc*Dc, ffb2 + Dc, nullptr,
         out + (size_t)BLc*Dc, nullptr, BLc, Dc, Fc, Dc, 0, 0);
    g256(sB, T2, w1, ffb1, nullptr, nullptr, H0, BLc, Fc, Dc, Fc, 0, 1);
    g128(sB, H0, w2, ffb2, nullptr, out, nullptr, BLc, Dc, Fc, Dc, 0, 0);
    join();
}

// round 13
// speedup vs baseline: 1.0719x; 1.0719x over previous
#include <cuda_runtime.h>
#include <cuda_fp16.h>
#include <math.h>
#include <stdint.h>

// Problem constants
constexpr int Bc  = 4;
constexpr int Lc  = 1024;
constexpr int Dc  = 1024;
constexpr int Fc  = 4096;
constexpr int HDc = 64;
constexpr int BLc = Bc * Lc;          // 4096 rows
constexpr int QKVW = 3 * Dc;          // 3072 concat width

// ---------------------------------------------------------------------------
// Scratch (static __device__ arrays — allocation-free per harness rules)
// ---------------------------------------------------------------------------
__device__ float g_Mo0[BLc * Dc];
__device__ float g_Mo1[BLc * Dc];
__device__ float g_T1f[BLc * Dc];
__device__ float g_A1f[BLc * Dc];

__device__ __half g_iT [BLc*Dc], g_iA [BLc*Dc];
__device__ __half g_T1 [BLc*Dc], g_A1 [BLc*Dc];
__device__ __half g_T2 [BLc*Dc], g_A2 [BLc*Dc];
__device__ __half g_O0 [BLc*Dc], g_O1 [BLc*Dc];
__device__ __half g_H0 [(size_t)BLc*Fc], g_H1 [(size_t)BLc*Fc];
__device__ __half g_QKV0[(size_t)BLc*QKVW];
__device__ __half g_QKV1[(size_t)BLc*QKVW];

// weights: single fp16, concat QKV^T [4][3072,1024]; others [N,K]
__device__ __half g_wc[(size_t)4*QKVW*Dc];
__device__ __half g_wo[4*Dc*Dc];
__device__ __half g_w1[2*Dc*Fc];
__device__ __half g_w2[2*Fc*Dc];
__device__ float g_bcat[4*QKVW];

// ---------------------------------------------------------------------------
// PTX helpers (sm_103 baseline-safe)
// ---------------------------------------------------------------------------
__device__ __forceinline__ uint32_t smem_u32(const void* p) {
    uint32_t a;
    asm("{ .reg .u64 t; cvta.to.shared.u64 t, %1; cvt.u32.u64 %0, t; }" : "=r"(a) : "l"(p));
    return a;
}
__device__ __forceinline__ void cpasync16(uint32_t dst, const void* src) {
    asm volatile("cp.async.cg.shared.global [%0], [%1], 16;" :: "r"(dst), "l"(src));
}
#define CP_COMMIT()  asm volatile("cp.async.commit_group;" ::: "memory")
#define CP_WAIT(n)   asm volatile("cp.async.wait_group %0;" :: "n"(n) : "memory")

#define LDSM4(r, a) \
    asm volatile("ldmatrix.sync.aligned.m8n8.x4.shared.b16 {%0,%1,%2,%3}, [%4];" \
        : "=r"((r)[0]), "=r"((r)[1]), "=r"((r)[2]), "=r"((r)[3]) : "r"(a))
#define LDSM4T(r, a) \
    asm volatile("ldmatrix.sync.aligned.m8n8.x4.trans.shared.b16 {%0,%1,%2,%3}, [%4];" \
        : "=r"((r)[0]), "=r"((r)[1]), "=r"((r)[2]), "=r"((r)[3]) : "r"(a))

__device__ __forceinline__ void mma16816(float* c, const uint32_t* a, const uint32_t* b) {
    asm volatile(
        "mma.sync.aligned.m16n8k16.row.col.f32.f16.f16.f32 "
        "{%0,%1,%2,%3}, {%4,%5,%6,%7}, {%8,%9}, {%0,%1,%2,%3};"
        : "+f"(c[0]), "+f"(c[1]), "+f"(c[2]), "+f"(c[3])
        : "r"(a[0]), "r"(a[1]), "r"(a[2]), "r"(a[3]), "r"(b[0]), "r"(b[1]));
}

__device__ __forceinline__ uint32_t packh(float a, float b) {
    __half2 t; t.x = __float2half(a); t.y = __float2half(b);
    return *(uint32_t*)&t;
}
#define FSW(o) ((o) ^ (((o) >> 3) & 0x70))     // SW128 swizzle for 128B rows

// ---------------------------------------------------------------------------
// Tensor-core GEMM (BM=128, 256 thr, occ 2 — the proven config).
// C[M,N] = A[M,K] @ B[N,K]^T (+bias)(+resid)(+relu); single fp16, fp32 acc;
// 3-stage cp.async. Output fp32 (C) and/or fp16 (Ch). ldc stride, coff offset.
// ---------------------------------------------------------------------------
constexpr int GSTR    = 40;
constexpr int TILE_B  = 128 * GSTR * 2;       // 10240 B per tile
constexpr int STAGE_B = 2 * TILE_B;           // A, B = 20480 B
constexpr int GEMM_SMEM = 3 * STAGE_B;        // 61440 B (3 stages)

__global__ __launch_bounds__(256, 2) void gemm_mma(
    const __half* __restrict__ Aa, const __half* __restrict__ Bb,
    const float* __restrict__ bias, const float* __restrict__ resid,
    float* __restrict__ C, __half* __restrict__ Ch,
    int M, int N, int K, int ldc, int coff, int relu)
{
    extern __shared__ char sm[];
    const uint32_t sb = smem_u32(sm);
    const int tid  = threadIdx.x;
    const int wid  = tid >> 5;
    const int lane = tid & 31;
    const int brow = blockIdx.y * 128;
    const int bcol = blockIdx.x * 128;
    const int wm   = (wid & 1) * 64;
    const int wn   = (wid >> 1) * 32;

    float acc[4][4][4];
    #pragma unroll
    for (int i = 0; i < 4; i++)
        #pragma unroll
        for (int j = 0; j < 4; j++)
            #pragma unroll
            for (int k = 0; k < 4; k++) acc[i][j][k] = 0.f;

    const int r0 = tid >> 2,            q0 = tid & 3;
    const int r1 = (tid + 256) >> 2,    q1 = (tid + 256) & 3;
    const int nch = K >> 5;

    auto issue = [&](int c, int s) {
        const int kc = c << 5;
        const uint32_t st = sb + s * STAGE_B;
        {
            const uint32_t so = (uint32_t)(r0 * 80 + q0 * 16);
            cpasync16(st + so,          Aa + (size_t)(brow + r0) * K + kc + q0 * 8);
            cpasync16(st + TILE_B + so, Bb + (size_t)(bcol + r0) * K + kc + q0 * 8);
        }
        {
            const uint32_t so = (uint32_t)(r1 * 80 + q1 * 16);
            cpasync16(st + so,          Aa + (size_t)(brow + r1) * K + kc + q1 * 8);
            cpasync16(st + TILE_B + so, Bb + (size_t)(bcol + r1) * K + kc + q1 * 8);
        }
        CP_COMMIT();
    };

    issue(0, 0);
    if (nch > 1) issue(1, 1);

    const int a_row = (lane & 15);
    const int a_kof = ((lane >> 4) << 3);
    const int g8    = lane >> 3;
    const int b_nt  = (g8 >> 1) << 3;
    const int b_kof = (g8 & 1) << 3;
    const int b_row = (lane & 7);

    for (int c = 0; c < nch; c++) {
        if (c + 2 < nch) { issue(c + 2, (c + 2) % 3); CP_WAIT(2); }
        else if (c + 1 < nch) CP_WAIT(1);
        else CP_WAIT(0);
        __syncthreads();

        const uint32_t st = sb + (c % 3) * STAGE_B;
        #pragma unroll
        for (int k16 = 0; k16 < 32; k16 += 16) {
            uint32_t aH[4][4], t[4];
            #pragma unroll
            for (int mt = 0; mt < 4; mt++) {
                uint32_t ad = st + (uint32_t)((wm + mt*16 + a_row) * 80
                                              + (k16 + a_kof) * 2);
                LDSM4(aH[mt], ad);
            }
            #pragma unroll
            for (int p = 0; p < 2; p++) {
                uint32_t ad = st + TILE_B
                    + (uint32_t)((wn + p*16 + b_nt + b_row) * 80
                                 + (k16 + b_kof) * 2);
                LDSM4(t, ad);
                uint32_t b0[2] = { t[0], t[1] }, b1[2] = { t[2], t[3] };
                #pragma unroll
                for (int mt = 0; mt < 4; mt++) {
                    mma16816(acc[mt][2*p    ], aH[mt], b0);
                    mma16816(acc[mt][2*p + 1], aH[mt], b1);
                }
            }
        }
        __syncthreads();
    }

    const int g  = lane >> 2;
    const int tg = lane & 3;
    #pragma unroll
    for (int mt = 0; mt < 4; mt++) {
        #pragma unroll
        for (int nt = 0; nt < 4; nt++) {
            const int row = brow + wm + mt*16 + g;
            const int col = bcol + wn + nt*8 + tg*2;
            float2 v0, v1;
            v0.x = acc[mt][nt][0]; v0.y = acc[mt][nt][1];
            v1.x = acc[mt][nt][2]; v1.y = acc[mt][nt][3];
            if (bias) {
                float2 bb = *(const float2*)&bias[col];
                v0.x += bb.x; v0.y += bb.y; v1.x += bb.x; v1.y += bb.y;
            }
            const size_t o0 = (size_t)row * ldc + coff + col;
            const size_t o1 = (size_t)(row + 8) * ldc + coff + col;
            if (resid) {
                float2 r0 = *(const float2*)&resid[o0];
                float2 r1 = *(const float2*)&resid[o1];
                v0.x += r0.x; v0.y += r0.y; v1.x += r1.x; v1.y += r1.y;
            }
            if (relu) {
                v0.x = fmaxf(v0.x, 0.f); v0.y = fmaxf(v0.y, 0.f);
                v1.x = fmaxf(v1.x, 0.f); v1.y = fmaxf(v1.y, 0.f);
            }
            if (C) {
                *(float2*)&C[o0] = v0;
                *(float2*)&C[o1] = v1;
            }
            if (Ch) {
                *(uint32_t*)&Ch[o0] = packh(v0.x, v0.y);
                *(uint32_t*)&Ch[o1] = packh(v1.x, v1.y);
            }
        }
    }
}

// ---------------------------------------------------------------------------
// Fused flash attention: single fp16, fp32 acc, occ 2, 3-stage KV pipeline.
// ---------------------------------------------------------------------------
constexpr int FA_QTB   = 128 * 144;               // 18432 B
constexpr int FA_KTB   = 64 * 128;                // 8192 B
constexpr int FA_STAGE = 2 * FA_KTB;              // K,V = 16384 B
constexpr int FA_SMEM  = FA_QTB + 3*FA_STAGE + 4096;   // 71680 B

__global__ __launch_bounds__(256, 2) void flash_attn(
    const __half* __restrict__ X,
    const float* __restrict__ mask, const int* __restrict__ pad,
    __half* __restrict__ O)
{
    extern __shared__ char sm[];
    const uint32_t sb = smem_u32(sm);
    const int tid  = threadIdx.x;
    const int wid  = tid >> 5;
    const int lane = tid & 31;
    const int qy   = blockIdx.x * 128;
    const int bh   = blockIdx.y;
    const int b    = bh >> 4;
    const int hcol = (bh & 15) * HDc;
    const int wq   = wid * 16;

    const uint32_t sQ     = sb;
    const uint32_t sStage = sb + FA_QTB;
    float* spad = (float*)(sm + FA_QTB + 3*FA_STAGE);

    for (int i = tid; i < 1024; i += 256)
        spad[i] = (float)pad[b*Lc + i];

    for (int i = tid; i < 1024; i += 256) {
        const int r = i >> 3, j = i & 7;
        const uint32_t so = (uint32_t)(r * 144 + j * 16);
        cpasync16(sQ + so, X + (size_t)(b*Lc + qy + r) * QKVW + hcol + j*8);
    }
    CP_COMMIT();

    auto issueKV = [&](int t, int s) {
        const int kx = t * 64;
        const uint32_t base = sStage + s * FA_STAGE;
        for (int i = tid; i < 512; i += 256) {
            const int r = i >> 3, j = i & 7;
            const uint32_t so = FSW((uint32_t)(r * 128 + j * 16));
            const size_t gk = (size_t)(b*Lc + kx + r) * QKVW + 1024 + hcol + j*8;
            cpasync16(base + so,            X + gk);
            cpasync16(base + FA_KTB + so,   X + gk + 1024);
        }
        CP_COMMIT();
    };
    issueKV(0, 0);
    issueKV(1, 1);

    CP_WAIT(2);          // Q complete
    __syncthreads();

    const int a_row = lane & 15;
    const int a_kof = (lane >> 4) << 3;
    uint32_t qh[4][4];
    #pragma unroll
    for (int kt = 0; kt < 4; kt++)
        LDSM4(qh[kt], sQ + (uint32_t)((wq + a_row)*144 + (kt*16 + a_kof)*2));

    float m[2] = { -1e30f, -1e30f };
    float l[2] = { 0.f, 0.f };
    float o[8][4];
    #pragma unroll
    for (int i = 0; i < 8; i++)
        #pragma unroll
        for (int j = 0; j < 4; j++) o[i][j] = 0.f;

    const int g    = lane >> 2;
    const int tg   = lane & 3;
    const int g8   = lane >> 3;
    const int b_nt  = (g8 >> 1) << 3;
    const int b_kof = (g8 & 1) << 3;
    const int b_row = lane & 7;
    const int v_kv = ((lane >> 3) & 1) << 3;
    const int v_d  = (lane >> 4) << 3;

    for (int t = 0; t < 16; t++) {
        const int kx = t * 64;
        if (t + 2 < 16) { issueKV(t + 2, (t + 2) % 3); CP_WAIT(2); }
        else if (t + 1 < 16) CP_WAIT(1);
        else CP_WAIT(0);
        __syncthreads();

        const uint32_t stK = sStage + (t % 3) * FA_STAGE;
        const uint32_t stV = stK + FA_KTB;

        float sf[8][4];
        #pragma unroll
        for (int i = 0; i < 8; i++)
            #pragma unroll
            for (int j = 0; j < 4; j++) sf[i][j] = 0.f;

        #pragma unroll
        for (int kst = 0; kst < 4; kst++) {
            uint32_t kb[4][4];
            #pragma unroll
            for (int p = 0; p < 4; p++) {
                const uint32_t ad = stK + FSW((uint32_t)((p*16 + b_nt + b_row)*128
                                                          + kst*32 + b_kof*2));
                LDSM4(kb[p], ad);
            }
            #pragma unroll
            for (int p = 0; p < 4; p++) {
                uint32_t b0[2] = { kb[p][0], kb[p][1] };
                uint32_t b1[2] = { kb[p][2], kb[p][3] };
                mma16816(sf[2*p],   qh[kst], b0);
                mma16816(sf[2*p+1], qh[kst], b1);
            }
        }

        const int qg0 = qy + wq + g;
        #pragma unroll
        for (int nt = 0; nt < 8; nt++) {
            const int kvl = nt*8 + tg*2;
            const int kvg = kx + kvl;
            float2 m0 = *(const float2*)&mask[(size_t)qg0 * Lc + kvg];
            float2 m1 = *(const float2*)&mask[(size_t)(qg0 + 8) * Lc + kvg];
            const float p0 = spad[kvg], p1 = spad[kvg + 1];
            sf[nt][0] = sf[nt][0]*0.125f + m0.x + p0;
            sf[nt][1] = sf[nt][1]*0.125f + m0.y + p1;
            sf[nt][2] = sf[nt][2]*0.125f + m1.x + p0;
            sf[nt][3] = sf[nt][3]*0.125f + m1.y + p1;
        }

        float mx0 = m[0], mx1 = m[1];
        #pragma unroll
        for (int nt = 0; nt < 8; nt++) {
            mx0 = fmaxf(mx0, fmaxf(sf[nt][0], sf[nt][1]));
            mx1 = fmaxf(mx1, fmaxf(sf[nt][2], sf[nt][3]));
        }
        mx0 = fmaxf(mx0, __shfl_xor_sync(0xffffffffu, mx0, 1));
        mx0 = fmaxf(mx0, __shfl_xor_sync(0xffffffffu, mx0, 2));
        mx1 = fmaxf(mx1, __shfl_xor_sync(0xffffffffu, mx1, 1));
        mx1 = fmaxf(mx1, __shfl_xor_sync(0xffffffffu, mx1, 2));

        const float al0 = __expf(m[0] - mx0);
        const float al1 = __expf(m[1] - mx1);
        m[0] = mx0; m[1] = mx1;
        #pragma unroll
        for (int nt = 0; nt < 8; nt++) {
            o[nt][0] *= al0; o[nt][1] *= al0;
            o[nt][2] *= al1; o[nt][3] *= al1;
        }

        uint32_t ph[4][4];
        float s0 = 0.f, s1 = 0.f;
        #pragma unroll
        for (int j = 0; j < 4; j++) {
            float e00 = __expf(sf[2*j][0]   - mx0);
            float e01 = __expf(sf[2*j][1]   - mx0);
            float e10 = __expf(sf[2*j][2]   - mx1);
            float e11 = __expf(sf[2*j][3]   - mx1);
            float e20 = __expf(sf[2*j+1][0] - mx0);
            float e21 = __expf(sf[2*j+1][1] - mx0);
            float e30 = __expf(sf[2*j+1][2] - mx1);
            float e31 = __expf(sf[2*j+1][3] - mx1);
            s0 += e00 + e01 + e20 + e21;
            s1 += e10 + e11 + e30 + e31;
            ph[j][0] = packh(e00, e01);
            ph[j][1] = packh(e10, e11);
            ph[j][2] = packh(e20, e21);
            ph[j][3] = packh(e30, e31);
        }
        s0 += __shfl_xor_sync(0xffffffffu, s0, 1);
        s0 += __shfl_xor_sync(0xffffffffu, s0, 2);
        s1 += __shfl_xor_sync(0xffffffffu, s1, 1);
        s1 += __shfl_xor_sync(0xffffffffu, s1, 2);
        l[0] = l[0]*al0 + s0;
        l[1] = l[1]*al1 + s1;

        #pragma unroll
        for (int j = 0; j < 4; j++) {
            #pragma unroll
            for (int p = 0; p < 4; p++) {
                uint32_t th[4];
                const uint32_t off = FSW((uint32_t)((j*16 + v_kv + b_row)*128
                                                     + p*32 + v_d*2));
                LDSM4T(th, stV + off);
                uint32_t b0[2] = { th[0], th[1] }, b1[2] = { th[2], th[3] };
                mma16816(o[2*p],   ph[j], b0);
                mma16816(o[2*p+1], ph[j], b1);
            }
        }
        __syncthreads();
    }

    const float inv0 = 1.f / l[0];
    const float inv1 = 1.f / l[1];
    const int row = b*Lc + qy + wq + g;
    #pragma unroll
    for (int nt = 0; nt < 8; nt++) {
        const int col = hcol + nt*8 + tg*2;
        *(uint32_t*)&O[(size_t)row * Dc + col]       = packh(o[nt][0]*inv0, o[nt][1]*inv0);
        *(uint32_t*)&O[(size_t)(row + 8) * Dc + col] = packh(o[nt][2]*inv1, o[nt][3]*inv1);
    }
}

// ---------------------------------------------------------------------------
// small kernels
// ---------------------------------------------------------------------------
__global__ __launch_bounds__(256) void cvt_f16(
    const float* __restrict__ x, __half* __restrict__ h)
{
    const size_t i = ((size_t)blockIdx.x * 256 + threadIdx.x) * 4;
    float4 v = *(const float4*)(x + i);
    *(uint32_t*)(h + i)     = packh(v.x, v.y);
    *(uint32_t*)(h + i + 2) = packh(v.z, v.w);
}

__global__ __launch_bounds__(256) void transpose_cvt(
    const float* __restrict__ W, __half* __restrict__ h,
    int K, int N, size_t ostrideZ)
{
    __shared__ float t[32][33];
    const size_t ibase = (size_t)blockIdx.z * K * N;
    const size_t obase = (size_t)blockIdx.z * ostrideZ;
    const int k0 = blockIdx.y * 32, n0 = blockIdx.x * 32;
    const int tx = threadIdx.x & 31, ty = threadIdx.x >> 5;
    #pragma unroll
    for (int r = 0; r < 32; r += 8)
        t[ty + r][tx] = W[ibase + (size_t)(k0 + ty + r) * N + n0 + tx];
    __syncthreads();
    #pragma unroll
    for (int r = 0; r < 32; r += 8) {
        const size_t o = obase + (size_t)(n0 + ty + r) * K + k0 + tx;
        h[o] = __float2half(t[tx][ty + r]);
    }
}

__global__ void bias_cat(const float* __restrict__ bq, const float* __restrict__ bk,
                         const float* __restrict__ bv, float* __restrict__ o)
{
    const int i = blockIdx.x, seg = blockIdx.y, j = threadIdx.x;
    const float* src = (seg == 0) ? bq : (seg == 1) ? bk : bv;
    o[i*QKVW + seg*1024 + j] = src[i*1024 + j];
}

// LN over rows (res nullable: x may already hold the residual sum)
__global__ __launch_bounds__(256) void add_ln(
    const float* __restrict__ x, const float* __restrict__ res,
    const float* __restrict__ g, const float* __restrict__ bta,
    float* __restrict__ y, __half* __restrict__ yh)
{
    __shared__ float rs[8], rq[8];
    const int tid = threadIdx.x;
    const size_t base = (size_t)blockIdx.x * 1024 + tid * 4;

    float4 a = *(const float4*)&x[base];
    if (res) {
        float4 r = *(const float4*)&res[base];
        a.x += r.x; a.y += r.y; a.z += r.z; a.w += r.w;
    }

    float s = a.x + a.y + a.z + a.w;
    float q = a.x*a.x + a.y*a.y + a.z*a.z + a.w*a.w;
    #pragma unroll
    for (int o = 16; o > 0; o >>= 1) {
        s += __shfl_xor_sync(0xffffffffu, s, o);
        q += __shfl_xor_sync(0xffffffffu, q, o);
    }
    if ((tid & 31) == 0) { rs[tid >> 5] = s; rq[tid >> 5] = q; }
    __syncthreads();
    s = 0.f; q = 0.f;
    #pragma unroll
    for (int i = 0; i < 8; i++) { s += rs[i]; q += rq[i]; }

    const float mean = s * (1.f / 1024.f);
    const float var  = q * (1.f / 1024.f) - mean * mean;
    const float rstd = rsqrtf(var + 1e-5f);

    const int c = tid * 4;
    float4 gv = *(const float4*)&g[c];
    float4 bv = *(const float4*)&bta[c];
    float4 o;
    o.x = (a.x - mean) * rstd * gv.x + bv.x;
    o.y = (a.y - mean) * rstd * gv.y + bv.y;
    o.z = (a.z - mean) * rstd * gv.z + bv.z;
    o.w = (a.w - mean) * rstd * gv.w + bv.w;
    if (y) *(float4*)&y[base] = o;

    *(uint32_t*)&yh[base]     = packh(o.x, o.y);
    *(uint32_t*)&yh[base + 2] = packh(o.z, o.w);
}

// ---------------------------------------------------------------------------
// Launch orchestration — round 9 DAG; BM128 everywhere; residual-fused Wo
// ---------------------------------------------------------------------------
extern "C" void kernel_launch(void* const* d_in, const int* in_sizes, int n_in,
                              void* d_out, int out_size)
{
    const float* T    = (const float*)d_in[0];
    const float* A    = (const float*)d_in[1];
    const float* mask = (const float*)d_in[2];
    const int*   pad  = (const int*)  d_in[3];
    const float* Wq   = (const float*)d_in[4];
    const float* bq   = (const float*)d_in[5];
    const float* Wk   = (const float*)d_in[6];
    const float* bk   = (const float*)d_in[7];
    const float* Wv   = (const float*)d_in[8];
    const float* bv   = (const float*)d_in[9];
    const float* Wo   = (const float*)d_in[10];
    const float* ffW1 = (const float*)d_in[11];
    const float* ffb1 = (const float*)d_in[12];
    const float* ffW2 = (const float*)d_in[13];
    const float* ffb2 = (const float*)d_in[14];
    const float* lng  = (const float*)d_in[15];
    const float* lnb  = (const float*)d_in[16];
    float* out = (float*)d_out;

    static cudaStream_t sA = nullptr, sB = nullptr, sC = nullptr;
    static cudaEvent_t  eF = nullptr, eA = nullptr, eB = nullptr;
    static cudaEvent_t  eC = nullptr, eQ2 = nullptr, eKV2 = nullptr, eQ3 = nullptr;
    if (!sA) {
        cudaStreamCreateWithFlags(&sA, cudaStreamNonBlocking);
        cudaStreamCreateWithFlags(&sB, cudaStreamNonBlocking);
        cudaStreamCreateWithFlags(&sC, cudaStreamNonBlocking);
        cudaEventCreateWithFlags(&eF,  cudaEventDisableTiming);
        cudaEventCreateWithFlags(&eA,  cudaEventDisableTiming);
        cudaEventCreateWithFlags(&eB,  cudaEventDisableTiming);
        cudaEventCreateWithFlags(&eC,  cudaEventDisableTiming);
        cudaEventCreateWithFlags(&eQ2, cudaEventDisableTiming);
        cudaEventCreateWithFlags(&eKV2,cudaEventDisableTiming);
        cudaEventCreateWithFlags(&eQ3, cudaEventDisableTiming);
    }
    auto fork = [&]() {
        cudaEventRecord(eF, 0);
        cudaStreamWaitEvent(sA, eF, 0);
        cudaStreamWaitEvent(sB, eF, 0);
    };
    auto join = [&]() {
        cudaEventRecord(eA, sA);
        cudaEventRecord(eB, sB);
        cudaStreamWaitEvent(0, eA, 0);
        cudaStreamWaitEvent(0, eB, 0);
    };

    float *Mo0, *Mo1, *T1f, *A1f;
    cudaGetSymbolAddress((void**)&Mo0, g_Mo0);
    cudaGetSymbolAddress((void**)&Mo1, g_Mo1);
    cudaGetSymbolAddress((void**)&T1f, g_T1f);
    cudaGetSymbolAddress((void**)&A1f, g_A1f);

    __half *iT,*iA,*T1,*A1,*T2,*A2,*O0,*O1,*H0,*H1,*QKV0,*QKV1;
    __half *wc,*wo,*w1,*w2;
    float* bcat;
    cudaGetSymbolAddress((void**)&iT, g_iT);   cudaGetSymbolAddress((void**)&iA, g_iA);
    cudaGetSymbolAddress((void**)&T1, g_T1);   cudaGetSymbolAddress((void**)&A1, g_A1);
    cudaGetSymbolAddress((void**)&T2, g_T2);   cudaGetSymbolAddress((void**)&A2, g_A2);
    cudaGetSymbolAddress((void**)&O0, g_O0);   cudaGetSymbolAddress((void**)&O1, g_O1);
    cudaGetSymbolAddress((void**)&H0, g_H0);   cudaGetSymbolAddress((void**)&H1, g_H1);
    cudaGetSymbolAddress((void**)&QKV0, g_QKV0);
    cudaGetSymbolAddress((void**)&QKV1, g_QKV1);
    cudaGetSymbolAddress((void**)&wc, g_wc);   cudaGetSymbolAddress((void**)&wo, g_wo);
    cudaGetSymbolAddress((void**)&w1, g_w1);   cudaGetSymbolAddress((void**)&w2, g_w2);
    cudaGetSymbolAddress((void**)&bcat, g_bcat);

    cudaFuncSetAttribute(gemm_mma,   cudaFuncAttributeMaxDynamicSharedMemorySize, GEMM_SMEM);
    cudaFuncSetAttribute(flash_attn, cudaFuncAttributeMaxDynamicSharedMemorySize, FA_SMEM);

    const size_t DD = (size_t)Dc * Dc;
    const size_t WCZ = (size_t)QKVW * Dc;

    auto gemm = [&](cudaStream_t st, const __half* a, const __half* b,
                    const float* bias, const float* resid, float* c, __half* ch,
                    int M, int N, int K, int ldc, int coff, int relu) {
        gemm_mma<<<dim3(N/128, M/128), 256, GEMM_SMEM, st>>>(
            a, b, bias, resid, c, ch, M, N, K, ldc, coff, relu);
    };

    // ------- Phase 0: CRITICAL prep (sA/sB) + DEFERRED prep (sC) -------
    fork();
    cudaStreamWaitEvent(sC, eF, 0);
    transpose_cvt<<<dim3(32,32,2), 256, 0, sA>>>(Wq, wc,        Dc, Dc, WCZ);
    transpose_cvt<<<dim3(32,32,2), 256, 0, sA>>>(Wk, wc + DD,   Dc, Dc, WCZ);
    transpose_cvt<<<dim3(32,32,2), 256, 0, sA>>>(Wv, wc + 2*DD, Dc, Dc, WCZ);
    bias_cat<<<dim3(4,3), 1024, 0, sA>>>(bq, bk, bv, bcat);
    cvt_f16<<<BLc, 256, 0, sA>>>(T, iT);
    transpose_cvt<<<dim3(32,32,2), 256, 0, sB>>>(Wo, wo, Dc, Dc, DD);
    cvt_f16<<<BLc, 256, 0, sB>>>(A, iA);
    transpose_cvt<<<dim3(32,32,2), 256, 0, sC>>>(Wq + 2*DD, wc + 2*WCZ,        Dc, Dc, WCZ);
    transpose_cvt<<<dim3(32,32,2), 256, 0, sC>>>(Wk + 2*DD, wc + 2*WCZ + DD,   Dc, Dc, WCZ);
    transpose_cvt<<<dim3(32,32,2), 256, 0, sC>>>(Wv + 2*DD, wc + 2*WCZ + 2*DD, Dc, Dc, WCZ);
    transpose_cvt<<<dim3(32,32,2), 256, 0, sC>>>(Wo + 2*DD, wo + 2*DD, Dc, Dc, DD);
    transpose_cvt<<<dim3(128,32,2), 256, 0, sC>>>(ffW1, w1, Dc, Fc, (size_t)Dc*Fc);
    transpose_cvt<<<dim3(32,128,2), 256, 0, sC>>>(ffW2, w2, Fc, Dc, (size_t)Fc*Dc);
    cudaEventRecord(eC, sC);
    join();

    // ---------------- Phase 1: mha0 (T, sA) || mha1 (A, sB) ----------------
    fork();
    gemm(sA, iT, wc, bcat, nullptr, nullptr, QKV0, BLc, QKVW, Dc, QKVW, 0, 0);
    flash_attn<<<dim3(Lc/128, 64), 256, FA_SMEM, sA>>>(QKV0, mask, pad, O0);
    gemm(sA, O0, wo, nullptr, T, Mo0, nullptr, BLc, Dc, Dc, Dc, 0, 0);   // Mo0 = O0@Wo + T
    add_ln<<<BLc, 256, 0, sA>>>(Mo0, nullptr, lng, lnb, T1f, T1);
    gemm(sB, iA, wc + WCZ, bcat + QKVW, nullptr, nullptr, QKV1, BLc, QKVW, Dc, QKVW, 0, 0);
    flash_attn<<<dim3(Lc/128, 64), 256, FA_SMEM, sB>>>(QKV1, mask, pad, O1);
    gemm(sB, O1, wo + DD, nullptr, A, Mo1, nullptr, BLc, Dc, Dc, Dc, 0, 0);
    add_ln<<<BLc, 256, 0, sB>>>(Mo1, nullptr, lng + Dc, lnb + Dc, A1f, A1);
    join();
    cudaStreamWaitEvent(0, eC, 0);

    // ------- Phase 2: KV2 (sA) || Q2,Q3 (sB); flash2 waits only {KV2,Q2} -------
    fork();
    gemm(sA, A1, wc + 2*WCZ + DD, bcat + 2*QKVW + 1024, nullptr,
         nullptr, QKV0, BLc, 2*Dc, Dc, QKVW, 1024, 0);
    cudaEventRecord(eKV2, sA);
    gemm(sB, T1, wc + 2*WCZ, bcat + 2*QKVW, nullptr, nullptr, QKV0,
         BLc, Dc, Dc, QKVW, 0, 0);
    cudaEventRecord(eQ2, sB);
    gemm(sB, A1, wc + 3*WCZ, bcat + 3*QKVW, nullptr, nullptr, QKV1,
         BLc, Dc, Dc, QKVW, 0, 0);
    cudaEventRecord(eQ3, sB);

    cudaStreamWaitEvent(0, eKV2, 0);
    cudaStreamWaitEvent(0, eQ2, 0);
    flash_attn<<<dim3(Lc/128, 64), 256, FA_SMEM>>>(QKV0, mask, pad, O0);
    gemm(0, O0, wo + 2*DD, nullptr, T1f, Mo0, nullptr, BLc, Dc, Dc, Dc, 0, 0);
    add_ln<<<BLc, 256>>>(Mo0, nullptr, lng + 2*Dc, lnb + 2*Dc, nullptr, T2);

    // ------- Phase 3: mha3 chain + FFN-A (sA)  ||  FFN-T (sB) -------
    fork();
    gemm(sA, T2, wc + 3*WCZ + DD, bcat + 3*QKVW + 1024, nullptr,
         nullptr, QKV1, BLc, 2*Dc, Dc, QKVW, 1024, 0);
    cudaStreamWaitEvent(sA, eQ3, 0);
    flash_attn<<<dim3(Lc/128, 64), 256, FA_SMEM, sA>>>(QKV1, mask, pad, O0);
    gemm(sA, O0, wo + 3*DD, nullptr, A1f, Mo0, nullptr, BLc, Dc, Dc, Dc, 0, 0);
    add_ln<<<BLc, 256, 0, sA>>>(Mo0, nullptr, lng + 3*Dc, lnb + 3*Dc, nullptr, A2);
    gemm(sA, A2, w1 + (size_t)Dc*Fc, ffb1 + Fc, nullptr, nullptr, H1,
         BLc, Fc, Dc, Fc, 0, 1);
    gemm(sA, H1, w2 + (size_t)Fc*Dc, ffb2 + Dc, nullptr,
         out + (size_t)BLc*Dc, nullptr, BLc, Dc, Fc, Dc, 0, 0);
    gemm(sB, T2, w1, ffb1, nullptr, nullptr, H0, BLc, Fc, Dc, Fc, 0, 1);
    gemm(sB, H0, w2, ffb2, nullptr, out, nullptr, BLc, Dc, Fc, Dc, 0, 0);
    join();
}

// round 14
// speedup vs baseline: 1.0833x; 1.0107x over previous
#include <cuda_runtime.h>
#include <cuda_fp16.h>
#include <math.h>
#include <stdint.h>

// Problem constants
constexpr int Bc  = 4;
constexpr int Lc  = 1024;
constexpr int Dc  = 1024;
constexpr int Fc  = 4096;
constexpr int HDc = 64;
constexpr int BLc = Bc * Lc;          // 4096 rows
constexpr int QKVW = 3 * Dc;          // 3072 concat width

// ---------------------------------------------------------------------------
// Scratch (static __device__ arrays — allocation-free per harness rules)
// ---------------------------------------------------------------------------
__device__ float g_Mo0[BLc * Dc];
__device__ float g_Mo1[BLc * Dc];
__device__ float g_T1f[BLc * Dc];
__device__ float g_A1f[BLc * Dc];

__device__ __half g_iT [BLc*Dc], g_iA [BLc*Dc];
__device__ __half g_T1 [BLc*Dc], g_A1 [BLc*Dc];
__device__ __half g_T2 [BLc*Dc], g_A2 [BLc*Dc];
__device__ __half g_O0 [BLc*Dc], g_O1 [BLc*Dc];
__device__ __half g_H0 [(size_t)BLc*Fc], g_H1 [(size_t)BLc*Fc];
__device__ __half g_QKV0[(size_t)BLc*QKVW];
__device__ __half g_QKV1[(size_t)BLc*QKVW];

// weights: single fp16, concat QKV^T [4][3072,1024]; others [N,K]
__device__ __half g_wc[(size_t)4*QKVW*Dc];
__device__ __half g_wo[4*Dc*Dc];
__device__ __half g_w1[2*Dc*Fc];
__device__ __half g_w2[2*Fc*Dc];
__device__ float g_bcat[4*QKVW];

// ---------------------------------------------------------------------------
// PTX helpers (sm_103 baseline-safe)
// ---------------------------------------------------------------------------
__device__ __forceinline__ uint32_t smem_u32(const void* p) {
    uint32_t a;
    asm("{ .reg .u64 t; cvta.to.shared.u64 t, %1; cvt.u32.u64 %0, t; }" : "=r"(a) : "l"(p));
    return a;
}
__device__ __forceinline__ void cpasync16(uint32_t dst, const void* src) {
    asm volatile("cp.async.cg.shared.global [%0], [%1], 16;" :: "r"(dst), "l"(src));
}
#define CP_COMMIT()  asm volatile("cp.async.commit_group;" ::: "memory")
#define CP_WAIT(n)   asm volatile("cp.async.wait_group %0;" :: "n"(n) : "memory")

#define LDSM4(r, a) \
    asm volatile("ldmatrix.sync.aligned.m8n8.x4.shared.b16 {%0,%1,%2,%3}, [%4];" \
        : "=r"((r)[0]), "=r"((r)[1]), "=r"((r)[2]), "=r"((r)[3]) : "r"(a))
#define LDSM4T(r, a) \
    asm volatile("ldmatrix.sync.aligned.m8n8.x4.trans.shared.b16 {%0,%1,%2,%3}, [%4];" \
        : "=r"((r)[0]), "=r"((r)[1]), "=r"((r)[2]), "=r"((r)[3]) : "r"(a))

__device__ __forceinline__ void mma16816(float* c, const uint32_t* a, const uint32_t* b) {
    asm volatile(
        "mma.sync.aligned.m16n8k16.row.col.f32.f16.f16.f32 "
        "{%0,%1,%2,%3}, {%4,%5,%6,%7}, {%8,%9}, {%0,%1,%2,%3};"
        : "+f"(c[0]), "+f"(c[1]), "+f"(c[2]), "+f"(c[3])
        : "r"(a[0]), "r"(a[1]), "r"(a[2]), "r"(a[3]), "r"(b[0]), "r"(b[1]));
}

__device__ __forceinline__ uint32_t packh(float a, float b) {
    __half2 t; t.x = __float2half(a); t.y = __float2half(b);
    return *(uint32_t*)&t;
}
#define FSW(o) ((o) ^ (((o) >> 3) & 0x70))     // SW128 swizzle for 128B rows

// ---------------------------------------------------------------------------
// Tensor-core GEMM (BM=128, 256 thr, occ 2; 3-stage cp.async).
// C[M,N] = A[M,K] @ B[N,K]^T (+bias)(+resid)(+relu); single fp16, fp32 acc.
// Output fp32 (C) and/or fp16 (Ch). ldc stride, coff offset.
// ---------------------------------------------------------------------------
constexpr int GSTR    = 40;
constexpr int TILE_B  = 128 * GSTR * 2;       // 10240 B per tile
constexpr int STAGE_B = 2 * TILE_B;           // A, B = 20480 B
constexpr int GEMM_SMEM = 3 * STAGE_B;        // 61440 B (3 stages)

__global__ __launch_bounds__(256, 2) void gemm_mma(
    const __half* __restrict__ Aa, const __half* __restrict__ Bb,
    const float* __restrict__ bias, const float* __restrict__ resid,
    float* __restrict__ C, __half* __restrict__ Ch,
    int M, int N, int K, int ldc, int coff, int relu)
{
    extern __shared__ char sm[];
    const uint32_t sb = smem_u32(sm);
    const int tid  = threadIdx.x;
    const int wid  = tid >> 5;
    const int lane = tid & 31;
    const int brow = blockIdx.y * 128;
    const int bcol = blockIdx.x * 128;
    const int wm   = (wid & 1) * 64;
    const int wn   = (wid >> 1) * 32;

    float acc[4][4][4];
    #pragma unroll
    for (int i = 0; i < 4; i++)
        #pragma unroll
        for (int j = 0; j < 4; j++)
            #pragma unroll
            for (int k = 0; k < 4; k++) acc[i][j][k] = 0.f;

    const int r0 = tid >> 2,            q0 = tid & 3;
    const int r1 = (tid + 256) >> 2,    q1 = (tid + 256) & 3;
    const int nch = K >> 5;

    auto issue = [&](int c, int s) {
        const int kc = c << 5;
        const uint32_t st = sb + s * STAGE_B;
        {
            const uint32_t so = (uint32_t)(r0 * 80 + q0 * 16);
            cpasync16(st + so,          Aa + (size_t)(brow + r0) * K + kc + q0 * 8);
            cpasync16(st + TILE_B + so, Bb + (size_t)(bcol + r0) * K + kc + q0 * 8);
        }
        {
            const uint32_t so = (uint32_t)(r1 * 80 + q1 * 16);
            cpasync16(st + so,          Aa + (size_t)(brow + r1) * K + kc + q1 * 8);
            cpasync16(st + TILE_B + so, Bb + (size_t)(bcol + r1) * K + kc + q1 * 8);
        }
        CP_COMMIT();
    };

    issue(0, 0);
    if (nch > 1) issue(1, 1);

    const int a_row = (lane & 15);
    const int a_kof = ((lane >> 4) << 3);
    const int g8    = lane >> 3;
    const int b_nt  = (g8 >> 1) << 3;
    const int b_kof = (g8 & 1) << 3;
    const int b_row = (lane & 7);

    for (int c = 0; c < nch; c++) {
        if (c + 2 < nch) { issue(c + 2, (c + 2) % 3); CP_WAIT(2); }
        else if (c + 1 < nch) CP_WAIT(1);
        else CP_WAIT(0);
        __syncthreads();

        const uint32_t st = sb + (c % 3) * STAGE_B;
        #pragma unroll
        for (int k16 = 0; k16 < 32; k16 += 16) {
            uint32_t aH[4][4], t[4];
            #pragma unroll
            for (int mt = 0; mt < 4; mt++) {
                uint32_t ad = st + (uint32_t)((wm + mt*16 + a_row) * 80
                                              + (k16 + a_kof) * 2);
                LDSM4(aH[mt], ad);
            }
            #pragma unroll
            for (int p = 0; p < 2; p++) {
                uint32_t ad = st + TILE_B
                    + (uint32_t)((wn + p*16 + b_nt + b_row) * 80
                                 + (k16 + b_kof) * 2);
                LDSM4(t, ad);
                uint32_t b0[2] = { t[0], t[1] }, b1[2] = { t[2], t[3] };
                #pragma unroll
                for (int mt = 0; mt < 4; mt++) {
                    mma16816(acc[mt][2*p    ], aH[mt], b0);
                    mma16816(acc[mt][2*p + 1], aH[mt], b1);
                }
            }
        }
        __syncthreads();
    }

    const int g  = lane >> 2;
    const int tg = lane & 3;
    #pragma unroll
    for (int mt = 0; mt < 4; mt++) {
        #pragma unroll
        for (int nt = 0; nt < 4; nt++) {
            const int row = brow + wm + mt*16 + g;
            const int col = bcol + wn + nt*8 + tg*2;
            float2 v0, v1;
            v0.x = acc[mt][nt][0]; v0.y = acc[mt][nt][1];
            v1.x = acc[mt][nt][2]; v1.y = acc[mt][nt][3];
            if (bias) {
                float2 bb = *(const float2*)&bias[col];
                v0.x += bb.x; v0.y += bb.y; v1.x += bb.x; v1.y += bb.y;
            }
            const size_t o0 = (size_t)row * ldc + coff + col;
            const size_t o1 = (size_t)(row + 8) * ldc + coff + col;
            if (resid) {
                float2 r0 = *(const float2*)&resid[o0];
                float2 r1 = *(const float2*)&resid[o1];
                v0.x += r0.x; v0.y += r0.y; v1.x += r1.x; v1.y += r1.y;
            }
            if (relu) {
                v0.x = fmaxf(v0.x, 0.f); v0.y = fmaxf(v0.y, 0.f);
                v1.x = fmaxf(v1.x, 0.f); v1.y = fmaxf(v1.y, 0.f);
            }
            if (C) {
                *(float2*)&C[o0] = v0;
                *(float2*)&C[o1] = v1;
            }
            if (Ch) {
                *(uint32_t*)&Ch[o0] = packh(v0.x, v0.y);
                *(uint32_t*)&Ch[o1] = packh(v1.x, v1.y);
            }
        }
    }
}

// ---------------------------------------------------------------------------
// Fused flash attention: single fp16, fp32 acc, occ 2, 2-STAGE KV pipeline
// (reverted to the R11 configuration).
// ---------------------------------------------------------------------------
constexpr int FA_QTB   = 128 * 144;               // 18432 B
constexpr int FA_KTB   = 64 * 128;                // 8192 B
constexpr int FA_STAGE = 2 * FA_KTB;              // K,V = 16384 B
constexpr int FA_SMEM  = FA_QTB + 2*FA_STAGE + 4096;   // 55296 B

__global__ __launch_bounds__(256, 2) void flash_attn(
    const __half* __restrict__ X,
    const float* __restrict__ mask, const int* __restrict__ pad,
    __half* __restrict__ O)
{
    extern __shared__ char sm[];
    const uint32_t sb = smem_u32(sm);
    const int tid  = threadIdx.x;
    const int wid  = tid >> 5;
    const int lane = tid & 31;
    const int qy   = blockIdx.x * 128;
    const int bh   = blockIdx.y;
    const int b    = bh >> 4;
    const int hcol = (bh & 15) * HDc;
    const int wq   = wid * 16;

    const uint32_t sQ     = sb;
    const uint32_t sStage = sb + FA_QTB;
    float* spad = (float*)(sm + FA_QTB + 2*FA_STAGE);

    for (int i = tid; i < 1024; i += 256)
        spad[i] = (float)pad[b*Lc + i];

    for (int i = tid; i < 1024; i += 256) {
        const int r = i >> 3, j = i & 7;
        const uint32_t so = (uint32_t)(r * 144 + j * 16);
        cpasync16(sQ + so, X + (size_t)(b*Lc + qy + r) * QKVW + hcol + j*8);
    }
    CP_COMMIT();

    auto issueKV = [&](int t, int s) {
        const int kx = t * 64;
        const uint32_t base = sStage + s * FA_STAGE;
        for (int i = tid; i < 512; i += 256) {
            const int r = i >> 3, j = i & 7;
            const uint32_t so = FSW((uint32_t)(r * 128 + j * 16));
            const size_t gk = (size_t)(b*Lc + kx + r) * QKVW + 1024 + hcol + j*8;
            cpasync16(base + so,            X + gk);
            cpasync16(base + FA_KTB + so,   X + gk + 1024);
        }
        CP_COMMIT();
    };
    issueKV(0, 0);

    CP_WAIT(1);          // Q complete
    __syncthreads();

    const int a_row = lane & 15;
    const int a_kof = (lane >> 4) << 3;
    uint32_t qh[4][4];
    #pragma unroll
    for (int kt = 0; kt < 4; kt++)
        LDSM4(qh[kt], sQ + (uint32_t)((wq + a_row)*144 + (kt*16 + a_kof)*2));

    float m[2] = { -1e30f, -1e30f };
    float l[2] = { 0.f, 0.f };
    float o[8][4];
    #pragma unroll
    for (int i = 0; i < 8; i++)
        #pragma unroll
        for (int j = 0; j < 4; j++) o[i][j] = 0.f;

    const int g    = lane >> 2;
    const int tg   = lane & 3;
    const int g8   = lane >> 3;
    const int b_nt  = (g8 >> 1) << 3;
    const int b_kof = (g8 & 1) << 3;
    const int b_row = lane & 7;
    const int v_kv = ((lane >> 3) & 1) << 3;
    const int v_d  = (lane >> 4) << 3;

    for (int t = 0; t < 16; t++) {
        const int kx = t * 64;
        if (t + 1 < 16) { issueKV(t + 1, (t + 1) & 1); CP_WAIT(1); }
        else            { CP_WAIT(0); }
        __syncthreads();

        const uint32_t stK = sStage + (t & 1) * FA_STAGE;
        const uint32_t stV = stK + FA_KTB;

        float sf[8][4];
        #pragma unroll
        for (int i = 0; i < 8; i++)
            #pragma unroll
            for (int j = 0; j < 4; j++) sf[i][j] = 0.f;

        #pragma unroll
        for (int kst = 0; kst < 4; kst++) {
            uint32_t kb[4][4];
            #pragma unroll
            for (int p = 0; p < 4; p++) {
                const uint32_t ad = stK + FSW((uint32_t)((p*16 + b_nt + b_row)*128
                                                          + kst*32 + b_kof*2));
                LDSM4(kb[p], ad);
            }
            #pragma unroll
            for (int p = 0; p < 4; p++) {
                uint32_t b0[2] = { kb[p][0], kb[p][1] };
                uint32_t b1[2] = { kb[p][2], kb[p][3] };
                mma16816(sf[2*p],   qh[kst], b0);
                mma16816(sf[2*p+1], qh[kst], b1);
            }
        }

        const int qg0 = qy + wq + g;
        #pragma unroll
        for (int nt = 0; nt < 8; nt++) {
            const int kvl = nt*8 + tg*2;
            const int kvg = kx + kvl;
            float2 m0 = *(const float2*)&mask[(size_t)qg0 * Lc + kvg];
            float2 m1 = *(const float2*)&mask[(size_t)(qg0 + 8) * Lc + kvg];
            const float p0 = spad[kvg], p1 = spad[kvg + 1];
            sf[nt][0] = sf[nt][0]*0.125f + m0.x + p0;
            sf[nt][1] = sf[nt][1]*0.125f + m0.y + p1;
            sf[nt][2] = sf[nt][2]*0.125f + m1.x + p0;
            sf[nt][3] = sf[nt][3]*0.125f + m1.y + p1;
        }

        float mx0 = m[0], mx1 = m[1];
        #pragma unroll
        for (int nt = 0; nt < 8; nt++) {
            mx0 = fmaxf(mx0, fmaxf(sf[nt][0], sf[nt][1]));
            mx1 = fmaxf(mx1, fmaxf(sf[nt][2], sf[nt][3]));
        }
        mx0 = fmaxf(mx0, __shfl_xor_sync(0xffffffffu, mx0, 1));
        mx0 = fmaxf(mx0, __shfl_xor_sync(0xffffffffu, mx0, 2));
        mx1 = fmaxf(mx1, __shfl_xor_sync(0xffffffffu, mx1, 1));
        mx1 = fmaxf(mx1, __shfl_xor_sync(0xffffffffu, mx1, 2));

        const float al0 = __expf(m[0] - mx0);
        const float al1 = __expf(m[1] - mx1);
        m[0] = mx0; m[1] = mx1;
        #pragma unroll
        for (int nt = 0; nt < 8; nt++) {
            o[nt][0] *= al0; o[nt][1] *= al0;
            o[nt][2] *= al1; o[nt][3] *= al1;
        }

        uint32_t ph[4][4];
        float s0 = 0.f, s1 = 0.f;
        #pragma unroll
        for (int j = 0; j < 4; j++) {
            float e00 = __expf(sf[2*j][0]   - mx0);
            float e01 = __expf(sf[2*j][1]   - mx0);
            float e10 = __expf(sf[2*j][2]   - mx1);
            float e11 = __expf(sf[2*j][3]   - mx1);
            float e20 = __expf(sf[2*j+1][0] - mx0);
            float e21 = __expf(sf[2*j+1][1] - mx0);
            float e30 = __expf(sf[2*j+1][2] - mx1);
            float e31 = __expf(sf[2*j+1][3] - mx1);
            s0 += e00 + e01 + e20 + e21;
            s1 += e10 + e11 + e30 + e31;
            ph[j][0] = packh(e00, e01);
            ph[j][1] = packh(e10, e11);
            ph[j][2] = packh(e20, e21);
            ph[j][3] = packh(e30, e31);
        }
        s0 += __shfl_xor_sync(0xffffffffu, s0, 1);
        s0 += __shfl_xor_sync(0xffffffffu, s0, 2);
        s1 += __shfl_xor_sync(0xffffffffu, s1, 1);
        s1 += __shfl_xor_sync(0xffffffffu, s1, 2);
        l[0] = l[0]*al0 + s0;
        l[1] = l[1]*al1 + s1;

        #pragma unroll
        for (int j = 0; j < 4; j++) {
            #pragma unroll
            for (int p = 0; p < 4; p++) {
                uint32_t th[4];
                const uint32_t off = FSW((uint32_t)((j*16 + v_kv + b_row)*128
                                                     + p*32 + v_d*2));
                LDSM4T(th, stV + off);
                uint32_t b0[2] = { th[0], th[1] }, b1[2] = { th[2], th[3] };
                mma16816(o[2*p],   ph[j], b0);
                mma16816(o[2*p+1], ph[j], b1);
            }
        }
        __syncthreads();
    }

    const float inv0 = 1.f / l[0];
    const float inv1 = 1.f / l[1];
    const int row = b*Lc + qy + wq + g;
    #pragma unroll
    for (int nt = 0; nt < 8; nt++) {
        const int col = hcol + nt*8 + tg*2;
        *(uint32_t*)&O[(size_t)row * Dc + col]       = packh(o[nt][0]*inv0, o[nt][1]*inv0);
        *(uint32_t*)&O[(size_t)(row + 8) * Dc + col] = packh(o[nt][2]*inv1, o[nt][3]*inv1);
    }
}

// ---------------------------------------------------------------------------
// small kernels
// ---------------------------------------------------------------------------
__global__ __launch_bounds__(256) void cvt_f16(
    const float* __restrict__ x, __half* __restrict__ h)
{
    const size_t i = ((size_t)blockIdx.x * 256 + threadIdx.x) * 4;
    float4 v = *(const float4*)(x + i);
    *(uint32_t*)(h + i)     = packh(v.x, v.y);
    *(uint32_t*)(h + i + 2) = packh(v.z, v.w);
}

__global__ __launch_bounds__(256) void transpose_cvt(
    const float* __restrict__ W, __half* __restrict__ h,
    int K, int N, size_t ostrideZ)
{
    __shared__ float t[32][33];
    const size_t ibase = (size_t)blockIdx.z * K * N;
    const size_t obase = (size_t)blockIdx.z * ostrideZ;
    const int k0 = blockIdx.y * 32, n0 = blockIdx.x * 32;
    const int tx = threadIdx.x & 31, ty = threadIdx.x >> 5;
    #pragma unroll
    for (int r = 0; r < 32; r += 8)
        t[ty + r][tx] = W[ibase + (size_t)(k0 + ty + r) * N + n0 + tx];
    __syncthreads();
    #pragma unroll
    for (int r = 0; r < 32; r += 8) {
        const size_t o = obase + (size_t)(n0 + ty + r) * K + k0 + tx;
        h[o] = __float2half(t[tx][ty + r]);
    }
}

__global__ void bias_cat(const float* __restrict__ bq, const float* __restrict__ bk,
                         const float* __restrict__ bv, float* __restrict__ o)
{
    const int i = blockIdx.x, seg = blockIdx.y, j = threadIdx.x;
    const float* src = (seg == 0) ? bq : (seg == 1) ? bk : bv;
    o[i*QKVW + seg*1024 + j] = src[i*1024 + j];
}

// LN over rows (res nullable: x may already hold the residual sum)
__global__ __launch_bounds__(256) void add_ln(
    const float* __restrict__ x, const float* __restrict__ res,
    const float* __restrict__ g, const float* __restrict__ bta,
    float* __restrict__ y, __half* __restrict__ yh)
{
    __shared__ float rs[8], rq[8];
    const int tid = threadIdx.x;
    const size_t base = (size_t)blockIdx.x * 1024 + tid * 4;

    float4 a = *(const float4*)&x[base];
    if (res) {
        float4 r = *(const float4*)&res[base];
        a.x += r.x; a.y += r.y; a.z += r.z; a.w += r.w;
    }

    float s = a.x + a.y + a.z + a.w;
    float q = a.x*a.x + a.y*a.y + a.z*a.z + a.w*a.w;
    #pragma unroll
    for (int o = 16; o > 0; o >>= 1) {
        s += __shfl_xor_sync(0xffffffffu, s, o);
        q += __shfl_xor_sync(0xffffffffu, q, o);
    }
    if ((tid & 31) == 0) { rs[tid >> 5] = s; rq[tid >> 5] = q; }
    __syncthreads();
    s = 0.f; q = 0.f;
    #pragma unroll
    for (int i = 0; i < 8; i++) { s += rs[i]; q += rq[i]; }

    const float mean = s * (1.f / 1024.f);
    const float var  = q * (1.f / 1024.f) - mean * mean;
    const float rstd = rsqrtf(var + 1e-5f);

    const int c = tid * 4;
    float4 gv = *(const float4*)&g[c];
    float4 bv = *(const float4*)&bta[c];
    float4 o;
    o.x = (a.x - mean) * rstd * gv.x + bv.x;
    o.y = (a.y - mean) * rstd * gv.y + bv.y;
    o.z = (a.z - mean) * rstd * gv.z + bv.z;
    o.w = (a.w - mean) * rstd * gv.w + bv.w;
    if (y) *(float4*)&y[base] = o;

    *(uint32_t*)&yh[base]     = packh(o.x, o.y);
    *(uint32_t*)&yh[base + 2] = packh(o.z, o.w);
}

// ---------------------------------------------------------------------------
// Launch orchestration — round 9 DAG; BM128; residual-fused Wo; 2-stage flash
// ---------------------------------------------------------------------------
extern "C" void kernel_launch(void* const* d_in, const int* in_sizes, int n_in,
                              void* d_out, int out_size)
{
    const float* T    = (const float*)d_in[0];
    const float* A    = (const float*)d_in[1];
    const float* mask = (const float*)d_in[2];
    const int*   pad  = (const int*)  d_in[3];
    const float* Wq   = (const float*)d_in[4];
    const float* bq   = (const float*)d_in[5];
    const float* Wk   = (const float*)d_in[6];
    const float* bk   = (const float*)d_in[7];
    const float* Wv   = (const float*)d_in[8];
    const float* bv   = (const float*)d_in[9];
    const float* Wo   = (const float*)d_in[10];
    const float* ffW1 = (const float*)d_in[11];
    const float* ffb1 = (const float*)d_in[12];
    const float* ffW2 = (const float*)d_in[13];
    const float* ffb2 = (const float*)d_in[14];
    const float* lng  = (const float*)d_in[15];
    const float* lnb  = (const float*)d_in[16];
    float* out = (float*)d_out;

    static cudaStream_t sA = nullptr, sB = nullptr, sC = nullptr;
    static cudaEvent_t  eF = nullptr, eA = nullptr, eB = nullptr;
    static cudaEvent_t  eC = nullptr, eQ2 = nullptr, eKV2 = nullptr, eQ3 = nullptr;
    if (!sA) {
        cudaStreamCreateWithFlags(&sA, cudaStreamNonBlocking);
        cudaStreamCreateWithFlags(&sB, cudaStreamNonBlocking);
        cudaStreamCreateWithFlags(&sC, cudaStreamNonBlocking);
        cudaEventCreateWithFlags(&eF,  cudaEventDisableTiming);
        cudaEventCreateWithFlags(&eA,  cudaEventDisableTiming);
        cudaEventCreateWithFlags(&eB,  cudaEventDisableTiming);
        cudaEventCreateWithFlags(&eC,  cudaEventDisableTiming);
        cudaEventCreateWithFlags(&eQ2, cudaEventDisableTiming);
        cudaEventCreateWithFlags(&eKV2,cudaEventDisableTiming);
        cudaEventCreateWithFlags(&eQ3, cudaEventDisableTiming);
    }
    auto fork = [&]() {
        cudaEventRecord(eF, 0);
        cudaStreamWaitEvent(sA, eF, 0);
        cudaStreamWaitEvent(sB, eF, 0);
    };
    auto join = [&]() {
        cudaEventRecord(eA, sA);
        cudaEventRecord(eB, sB);
        cudaStreamWaitEvent(0, eA, 0);
        cudaStreamWaitEvent(0, eB, 0);
    };

    float *Mo0, *Mo1, *T1f, *A1f;
    cudaGetSymbolAddress((void**)&Mo0, g_Mo0);
    cudaGetSymbolAddress((void**)&Mo1, g_Mo1);
    cudaGetSymbolAddress((void**)&T1f, g_T1f);
    cudaGetSymbolAddress((void**)&A1f, g_A1f);

    __half *iT,*iA,*T1,*A1,*T2,*A2,*O0,*O1,*H0,*H1,*QKV0,*QKV1;
    __half *wc,*wo,*w1,*w2;
    float* bcat;
    cudaGetSymbolAddress((void**)&iT, g_iT);   cudaGetSymbolAddress((void**)&iA, g_iA);
    cudaGetSymbolAddress((void**)&T1, g_T1);   cudaGetSymbolAddress((void**)&A1, g_A1);
    cudaGetSymbolAddress((void**)&T2, g_T2);   cudaGetSymbolAddress((void**)&A2, g_A2);
    cudaGetSymbolAddress((void**)&O0, g_O0);   cudaGetSymbolAddress((void**)&O1, g_O1);
    cudaGetSymbolAddress((void**)&H0, g_H0);   cudaGetSymbolAddress((void**)&H1, g_H1);
    cudaGetSymbolAddress((void**)&QKV0, g_QKV0);
    cudaGetSymbolAddress((void**)&QKV1, g_QKV1);
    cudaGetSymbolAddress((void**)&wc, g_wc);   cudaGetSymbolAddress((void**)&wo, g_wo);
    cudaGetSymbolAddress((void**)&w1, g_w1);   cudaGetSymbolAddress((void**)&w2, g_w2);
    cudaGetSymbolAddress((void**)&bcat, g_bcat);

    cudaFuncSetAttribute(gemm_mma,   cudaFuncAttributeMaxDynamicSharedMemorySize, GEMM_SMEM);
    cudaFuncSetAttribute(flash_attn, cudaFuncAttributeMaxDynamicSharedMemorySize, FA_SMEM);

    const size_t DD = (size_t)Dc * Dc;
    const size_t WCZ = (size_t)QKVW * Dc;

    auto gemm = [&](cudaStream_t st, const __half* a, const __half* b,
                    const float* bias, const float* resid, float* c, __half* ch,
                    int M, int N, int K, int ldc, int coff, int relu) {
        gemm_mma<<<dim3(N/128, M/128), 256, GEMM_SMEM, st>>>(
            a, b, bias, resid, c, ch, M, N, K, ldc, coff, relu);
    };

    // ------- Phase 0: CRITICAL prep (sA/sB) + DEFERRED prep (sC) -------
    fork();
    cudaStreamWaitEvent(sC, eF, 0);
    transpose_cvt<<<dim3(32,32,2), 256, 0, sA>>>(Wq, wc,        Dc, Dc, WCZ);
    transpose_cvt<<<dim3(32,32,2), 256, 0, sA>>>(Wk, wc + DD,   Dc, Dc, WCZ);
    transpose_cvt<<<dim3(32,32,2), 256, 0, sA>>>(Wv, wc + 2*DD, Dc, Dc, WCZ);
    bias_cat<<<dim3(4,3), 1024, 0, sA>>>(bq, bk, bv, bcat);
    cvt_f16<<<BLc, 256, 0, sA>>>(T, iT);
    transpose_cvt<<<dim3(32,32,2), 256, 0, sB>>>(Wo, wo, Dc, Dc, DD);
    cvt_f16<<<BLc, 256, 0, sB>>>(A, iA);
    transpose_cvt<<<dim3(32,32,2), 256, 0, sC>>>(Wq + 2*DD, wc + 2*WCZ,        Dc, Dc, WCZ);
    transpose_cvt<<<dim3(32,32,2), 256, 0, sC>>>(Wk + 2*DD, wc + 2*WCZ + DD,   Dc, Dc, WCZ);
    transpose_cvt<<<dim3(32,32,2), 256, 0, sC>>>(Wv + 2*DD, wc + 2*WCZ + 2*DD, Dc, Dc, WCZ);
    transpose_cvt<<<dim3(32,32,2), 256, 0, sC>>>(Wo + 2*DD, wo + 2*DD, Dc, Dc, DD);
    transpose_cvt<<<dim3(128,32,2), 256, 0, sC>>>(ffW1, w1, Dc, Fc, (size_t)Dc*Fc);
    transpose_cvt<<<dim3(32,128,2), 256, 0, sC>>>(ffW2, w2, Fc, Dc, (size_t)Fc*Dc);
    cudaEventRecord(eC, sC);
    join();

    // ---------------- Phase 1: mha0 (T, sA) || mha1 (A, sB) ----------------
    fork();
    gemm(sA, iT, wc, bcat, nullptr, nullptr, QKV0, BLc, QKVW, Dc, QKVW, 0, 0);
    flash_attn<<<dim3(Lc/128, 64), 256, FA_SMEM, sA>>>(QKV0, mask, pad, O0);
    gemm(sA, O0, wo, nullptr, T, Mo0, nullptr, BLc, Dc, Dc, Dc, 0, 0);   // Mo0 = O0@Wo + T
    add_ln<<<BLc, 256, 0, sA>>>(Mo0, nullptr, lng, lnb, T1f, T1);
    gemm(sB, iA, wc + WCZ, bcat + QKVW, nullptr, nullptr, QKV1, BLc, QKVW, Dc, QKVW, 0, 0);
    flash_attn<<<dim3(Lc/128, 64), 256, FA_SMEM, sB>>>(QKV1, mask, pad, O1);
    gemm(sB, O1, wo + DD, nullptr, A, Mo1, nullptr, BLc, Dc, Dc, Dc, 0, 0);
    add_ln<<<BLc, 256, 0, sB>>>(Mo1, nullptr, lng + Dc, lnb + Dc, A1f, A1);
    join();
    cudaStreamWaitEvent(0, eC, 0);

    // ------- Phase 2: KV2 (sA) || Q2,Q3 (sB); flash2 waits only {KV2,Q2} -------
    fork();
    gemm(sA, A1, wc + 2*WCZ + DD, bcat + 2*QKVW + 1024, nullptr,
         nullptr, QKV0, BLc, 2*Dc, Dc, QKVW, 1024, 0);
    cudaEventRecord(eKV2, sA);
    gemm(sB, T1, wc + 2*WCZ, bcat + 2*QKVW, nullptr, nullptr, QKV0,
         BLc, Dc, Dc, QKVW, 0, 0);
    cudaEventRecord(eQ2, sB);
    gemm(sB, A1, wc + 3*WCZ, bcat + 3*QKVW, nullptr, nullptr, QKV1,
         BLc, Dc, Dc, QKVW, 0, 0);
    cudaEventRecord(eQ3, sB);

    cudaStreamWaitEvent(0, eKV2, 0);
    cudaStreamWaitEvent(0, eQ2, 0);
    flash_attn<<<dim3(Lc/128, 64), 256, FA_SMEM>>>(QKV0, mask, pad, O0);
    gemm(0, O0, wo + 2*DD, nullptr, T1f, Mo0, nullptr, BLc, Dc, Dc, Dc, 0, 0);
    add_ln<<<BLc, 256>>>(Mo0, nullptr, lng + 2*Dc, lnb + 2*Dc, nullptr, T2);

    // ------- Phase 3: mha3 chain + FFN-A (sA)  ||  FFN-T (sB) -------
    fork();
    gemm(sA, T2, wc + 3*WCZ + DD, bcat + 3*QKVW + 1024, nullptr,
         nullptr, QKV1, BLc, 2*Dc, Dc, QKVW, 1024, 0);
    cudaStreamWaitEvent(sA, eQ3, 0);
    flash_attn<<<dim3(Lc/128, 64), 256, FA_SMEM, sA>>>(QKV1, mask, pad, O0);
    gemm(sA, O0, wo + 3*DD, nullptr, A1f, Mo0, nullptr, BLc, Dc, Dc, Dc, 0, 0);
    add_ln<<<BLc, 256, 0, sA>>>(Mo0, nullptr, lng + 3*Dc, lnb + 3*Dc, nullptr, A2);
    gemm(sA, A2, w1 + (size_t)Dc*Fc, ffb1 + Fc, nullptr, nullptr, H1,
         BLc, Fc, Dc, Fc, 0, 1);
    gemm(sA, H1, w2 + (size_t)Fc*Dc, ffb2 + Dc, nullptr,
         out + (size_t)BLc*Dc, nullptr, BLc, Dc, Fc, Dc, 0, 0);
    gemm(sB, T2, w1, ffb1, nullptr, nullptr, H0, BLc, Fc, Dc, Fc, 0, 1);
    gemm(sB, H0, w2, ffb2, nullptr, out, nullptr, BLc, Dc, Fc, Dc, 0, 0);
    join();
}

// round 15
// speedup vs baseline: 1.1596x; 1.0704x over previous
#include <cuda_runtime.h>
#include <cuda_fp16.h>
#include <math.h>
#include <stdint.h>

// Problem constants
constexpr int Bc  = 4;
constexpr int Lc  = 1024;
constexpr int Dc  = 1024;
constexpr int Fc  = 4096;
constexpr int HDc = 64;
constexpr int BLc = Bc * Lc;          // 4096 rows
constexpr int QKVW = 3 * Dc;          // 3072 concat width

// ---------------------------------------------------------------------------
// Scratch (static __device__ arrays — allocation-free per harness rules)
// ---------------------------------------------------------------------------
__device__ float g_Mo0[BLc * Dc];
__device__ float g_Mo1[BLc * Dc];
__device__ float g_T1f[BLc * Dc];
__device__ float g_A1f[BLc * Dc];

__device__ __half g_iT [BLc*Dc], g_iA [BLc*Dc];
__device__ __half g_T1 [BLc*Dc], g_A1 [BLc*Dc];
__device__ __half g_T2 [BLc*Dc], g_A2 [BLc*Dc];
__device__ __half g_O0 [BLc*Dc], g_O1 [BLc*Dc];
__device__ __half g_H0 [(size_t)BLc*Fc], g_H1 [(size_t)BLc*Fc];
__device__ __half g_QKV0[(size_t)BLc*QKVW];
__device__ __half g_QKV1[(size_t)BLc*QKVW];

// weights: single fp16, concat QKV^T [4][3072,1024]; others [N,K]
__device__ __half g_wc[(size_t)4*QKVW*Dc];
__device__ __half g_wo[4*Dc*Dc];
__device__ __half g_w1[2*Dc*Fc];
__device__ __half g_w2[2*Fc*Dc];
__device__ float g_bcat[4*QKVW];

// ---------------------------------------------------------------------------
// PTX helpers (sm_103 baseline-safe)
// ---------------------------------------------------------------------------
__device__ __forceinline__ uint32_t smem_u32(const void* p) {
    uint32_t a;
    asm("{ .reg .u64 t; cvta.to.shared.u64 t, %1; cvt.u32.u64 %0, t; }" : "=r"(a) : "l"(p));
    return a;
}
__device__ __forceinline__ void cpasync16(uint32_t dst, const void* src) {
    asm volatile("cp.async.cg.shared.global [%0], [%1], 16;" :: "r"(dst), "l"(src));
}
#define CP_COMMIT()  asm volatile("cp.async.commit_group;" ::: "memory")
#define CP_WAIT(n)   asm volatile("cp.async.wait_group %0;" :: "n"(n) : "memory")

#define LDSM4(r, a) \
    asm volatile("ldmatrix.sync.aligned.m8n8.x4.shared.b16 {%0,%1,%2,%3}, [%4];" \
        : "=r"((r)[0]), "=r"((r)[1]), "=r"((r)[2]), "=r"((r)[3]) : "r"(a))
#define LDSM4T(r, a) \
    asm volatile("ldmatrix.sync.aligned.m8n8.x4.trans.shared.b16 {%0,%1,%2,%3}, [%4];" \
        : "=r"((r)[0]), "=r"((r)[1]), "=r"((r)[2]), "=r"((r)[3]) : "r"(a))

__device__ __forceinline__ void mma16816(float* c, const uint32_t* a, const uint32_t* b) {
    asm volatile(
        "mma.sync.aligned.m16n8k16.row.col.f32.f16.f16.f32 "
        "{%0,%1,%2,%3}, {%4,%5,%6,%7}, {%8,%9}, {%0,%1,%2,%3};"
        : "+f"(c[0]), "+f"(c[1]), "+f"(c[2]), "+f"(c[3])
        : "r"(a[0]), "r"(a[1]), "r"(a[2]), "r"(a[3]), "r"(b[0]), "r"(b[1]));
}

__device__ __forceinline__ uint32_t packh(float a, float b) {
    __half2 t; t.x = __float2half(a); t.y = __float2half(b);
    return *(uint32_t*)&t;
}
#define FSW(o) ((o) ^ (((o) >> 3) & 0x70))     // SW128 swizzle for 128B rows

// ---------------------------------------------------------------------------
// Tensor-core GEMM (BM=128, 256 thr, occ 2): 4-stage cp.async, distance-2
// prefetch, SINGLE __syncthreads per chunk (WAR-safe: writer stage (c+3)%4
// never aliases any stage readable by a <=1-iteration straggler).
// C[M,N] = A[M,K] @ B[N,K]^T (+bias)(+resid)(+relu); single fp16, fp32 acc.
// ---------------------------------------------------------------------------
constexpr int GSTR    = 40;
constexpr int TILE_B  = 128 * GSTR * 2;       // 10240 B per tile
constexpr int STAGE_B = 2 * TILE_B;           // A, B = 20480 B
constexpr int GEMM_SMEM = 4 * STAGE_B;        // 81920 B (4 stages)

__global__ __launch_bounds__(256, 2) void gemm_mma(
    const __half* __restrict__ Aa, const __half* __restrict__ Bb,
    const float* __restrict__ bias, const float* __restrict__ resid,
    float* __restrict__ C, __half* __restrict__ Ch,
    int M, int N, int K, int ldc, int coff, int relu)
{
    extern __shared__ char sm[];
    const uint32_t sb = smem_u32(sm);
    const int tid  = threadIdx.x;
    const int wid  = tid >> 5;
    const int lane = tid & 31;
    const int brow = blockIdx.y * 128;
    const int bcol = blockIdx.x * 128;
    const int wm   = (wid & 1) * 64;
    const int wn   = (wid >> 1) * 32;

    float acc[4][4][4];
    #pragma unroll
    for (int i = 0; i < 4; i++)
        #pragma unroll
        for (int j = 0; j < 4; j++)
            #pragma unroll
            for (int k = 0; k < 4; k++) acc[i][j][k] = 0.f;

    const int r0 = tid >> 2,            q0 = tid & 3;
    const int r1 = (tid + 256) >> 2,    q1 = (tid + 256) & 3;
    const int nch = K >> 5;

    auto issue = [&](int c, int s) {
        const int kc = c << 5;
        const uint32_t st = sb + s * STAGE_B;
        {
            const uint32_t so = (uint32_t)(r0 * 80 + q0 * 16);
            cpasync16(st + so,          Aa + (size_t)(brow + r0) * K + kc + q0 * 8);
            cpasync16(st + TILE_B + so, Bb + (size_t)(bcol + r0) * K + kc + q0 * 8);
        }
        {
            const uint32_t so = (uint32_t)(r1 * 80 + q1 * 16);
            cpasync16(st + so,          Aa + (size_t)(brow + r1) * K + kc + q1 * 8);
            cpasync16(st + TILE_B + so, Bb + (size_t)(bcol + r1) * K + kc + q1 * 8);
        }
        CP_COMMIT();
    };

    issue(0, 0);
    if (nch > 1) issue(1, 1);

    const int a_row = (lane & 15);
    const int a_kof = ((lane >> 4) << 3);
    const int g8    = lane >> 3;
    const int b_nt  = (g8 >> 1) << 3;
    const int b_kof = (g8 & 1) << 3;
    const int b_row = (lane & 7);

    for (int c = 0; c < nch; c++) {
        if (c + 2 < nch) { issue(c + 2, (c + 2) & 3); CP_WAIT(2); }
        else if (c + 1 < nch) CP_WAIT(1);
        else CP_WAIT(0);
        __syncthreads();        // single barrier per chunk (leading)

        const uint32_t st = sb + (c & 3) * STAGE_B;
        #pragma unroll
        for (int k16 = 0; k16 < 32; k16 += 16) {
            uint32_t aH[4][4], t[4];
            #pragma unroll
            for (int mt = 0; mt < 4; mt++) {
                uint32_t ad = st + (uint32_t)((wm + mt*16 + a_row) * 80
                                              + (k16 + a_kof) * 2);
                LDSM4(aH[mt], ad);
            }
            #pragma unroll
            for (int p = 0; p < 2; p++) {
                uint32_t ad = st + TILE_B
                    + (uint32_t)((wn + p*16 + b_nt + b_row) * 80
                                 + (k16 + b_kof) * 2);
                LDSM4(t, ad);
                uint32_t b0[2] = { t[0], t[1] }, b1[2] = { t[2], t[3] };
                #pragma unroll
                for (int mt = 0; mt < 4; mt++) {
                    mma16816(acc[mt][2*p    ], aH[mt], b0);
                    mma16816(acc[mt][2*p + 1], aH[mt], b1);
                }
            }
        }
        // no trailing __syncthreads: 4-stage ring makes the WAR stage-disjoint
    }

    const int g  = lane >> 2;
    const int tg = lane & 3;
    #pragma unroll
    for (int mt = 0; mt < 4; mt++) {
        #pragma unroll
        for (int nt = 0; nt < 4; nt++) {
            const int row = brow + wm + mt*16 + g;
            const int col = bcol + wn + nt*8 + tg*2;
            float2 v0, v1;
            v0.x = acc[mt][nt][0]; v0.y = acc[mt][nt][1];
            v1.x = acc[mt][nt][2]; v1.y = acc[mt][nt][3];
            if (bias) {
                float2 bb = *(const float2*)&bias[col];
                v0.x += bb.x; v0.y += bb.y; v1.x += bb.x; v1.y += bb.y;
            }
            const size_t o0 = (size_t)row * ldc + coff + col;
            const size_t o1 = (size_t)(row + 8) * ldc + coff + col;
            if (resid) {
                float2 r0 = *(const float2*)&resid[o0];
                float2 r1 = *(const float2*)&resid[o1];
                v0.x += r0.x; v0.y += r0.y; v1.x += r1.x; v1.y += r1.y;
            }
            if (relu) {
                v0.x = fmaxf(v0.x, 0.f); v0.y = fmaxf(v0.y, 0.f);
                v1.x = fmaxf(v1.x, 0.f); v1.y = fmaxf(v1.y, 0.f);
            }
            if (C) {
                *(float2*)&C[o0] = v0;
                *(float2*)&C[o1] = v1;
            }
            if (Ch) {
                *(uint32_t*)&Ch[o0] = packh(v0.x, v0.y);
                *(uint32_t*)&Ch[o1] = packh(v1.x, v1.y);
            }
        }
    }
}

// ---------------------------------------------------------------------------
// Fused flash attention: single fp16, fp32 acc, occ 2, 2-stage KV (proven).
// ---------------------------------------------------------------------------
constexpr int FA_QTB   = 128 * 144;               // 18432 B
constexpr int FA_KTB   = 64 * 128;                // 8192 B
constexpr int FA_STAGE = 2 * FA_KTB;              // K,V = 16384 B
constexpr int FA_SMEM  = FA_QTB + 2*FA_STAGE + 4096;   // 55296 B

__global__ __launch_bounds__(256, 2) void flash_attn(
    const __half* __restrict__ X,
    const float* __restrict__ mask, const int* __restrict__ pad,
    __half* __restrict__ O)
{
    extern __shared__ char sm[];
    const uint32_t sb = smem_u32(sm);
    const int tid  = threadIdx.x;
    const int wid  = tid >> 5;
    const int lane = tid & 31;
    const int qy   = blockIdx.x * 128;
    const int bh   = blockIdx.y;
    const int b    = bh >> 4;
    const int hcol = (bh & 15) * HDc;
    const int wq   = wid * 16;

    const uint32_t sQ     = sb;
    const uint32_t sStage = sb + FA_QTB;
    float* spad = (float*)(sm + FA_QTB + 2*FA_STAGE);

    for (int i = tid; i < 1024; i += 256)
        spad[i] = (float)pad[b*Lc + i];

    for (int i = tid; i < 1024; i += 256) {
        const int r = i >> 3, j = i & 7;
        const uint32_t so = (uint32_t)(r * 144 + j * 16);
        cpasync16(sQ + so, X + (size_t)(b*Lc + qy + r) * QKVW + hcol + j*8);
    }
    CP_COMMIT();

    auto issueKV = [&](int t, int s) {
        const int kx = t * 64;
        const uint32_t base = sStage + s * FA_STAGE;
        for (int i = tid; i < 512; i += 256) {
            const int r = i >> 3, j = i & 7;
            const uint32_t so = FSW((uint32_t)(r * 128 + j * 16));
            const size_t gk = (size_t)(b*Lc + kx + r) * QKVW + 1024 + hcol + j*8;
            cpasync16(base + so,            X + gk);
            cpasync16(base + FA_KTB + so,   X + gk + 1024);
        }
        CP_COMMIT();
    };
    issueKV(0, 0);

    CP_WAIT(1);          // Q complete
    __syncthreads();

    const int a_row = lane & 15;
    const int a_kof = (lane >> 4) << 3;
    uint32_t qh[4][4];
    #pragma unroll
    for (int kt = 0; kt < 4; kt++)
        LDSM4(qh[kt], sQ + (uint32_t)((wq + a_row)*144 + (kt*16 + a_kof)*2));

    float m[2] = { -1e30f, -1e30f };
    float l[2] = { 0.f, 0.f };
    float o[8][4];
    #pragma unroll
    for (int i = 0; i < 8; i++)
        #pragma unroll
        for (int j = 0; j < 4; j++) o[i][j] = 0.f;

    const int g    = lane >> 2;
    const int tg   = lane & 3;
    const int g8   = lane >> 3;
    const int b_nt  = (g8 >> 1) << 3;
    const int b_kof = (g8 & 1) << 3;
    const int b_row = lane & 7;
    const int v_kv = ((lane >> 3) & 1) << 3;
    const int v_d  = (lane >> 4) << 3;

    for (int t = 0; t < 16; t++) {
        const int kx = t * 64;
        if (t + 1 < 16) { issueKV(t + 1, (t + 1) & 1); CP_WAIT(1); }
        else            { CP_WAIT(0); }
        __syncthreads();

        const uint32_t stK = sStage + (t & 1) * FA_STAGE;
        const uint32_t stV = stK + FA_KTB;

        float sf[8][4];
        #pragma unroll
        for (int i = 0; i < 8; i++)
            #pragma unroll
            for (int j = 0; j < 4; j++) sf[i][j] = 0.f;

        #pragma unroll
        for (int kst = 0; kst < 4; kst++) {
            uint32_t kb[4][4];
            #pragma unroll
            for (int p = 0; p < 4; p++) {
                const uint32_t ad = stK + FSW((uint32_t)((p*16 + b_nt + b_row)*128
                                                          + kst*32 + b_kof*2));
                LDSM4(kb[p], ad);
            }
            #pragma unroll
            for (int p = 0; p < 4; p++) {
                uint32_t b0[2] = { kb[p][0], kb[p][1] };
                uint32_t b1[2] = { kb[p][2], kb[p][3] };
                mma16816(sf[2*p],   qh[kst], b0);
                mma16816(sf[2*p+1], qh[kst], b1);
            }
        }

        const int qg0 = qy + wq + g;
        #pragma unroll
        for (int nt = 0; nt < 8; nt++) {
            const int kvl = nt*8 + tg*2;
            const int kvg = kx + kvl;
            float2 m0 = *(const float2*)&mask[(size_t)qg0 * Lc + kvg];
            float2 m1 = *(const float2*)&mask[(size_t)(qg0 + 8) * Lc + kvg];
            const float p0 = spad[kvg], p1 = spad[kvg + 1];
            sf[nt][0] = sf[nt][0]*0.125f + m0.x + p0;
            sf[nt][1] = sf[nt][1]*0.125f + m0.y + p1;
            sf[nt][2] = sf[nt][2]*0.125f + m1.x + p0;
            sf[nt][3] = sf[nt][3]*0.125f + m1.y + p1;
        }

        float mx0 = m[0], mx1 = m[1];
        #pragma unroll
        for (int nt = 0; nt < 8; nt++) {
            mx0 = fmaxf(mx0, fmaxf(sf[nt][0], sf[nt][1]));
            mx1 = fmaxf(mx1, fmaxf(sf[nt][2], sf[nt][3]));
        }
        mx0 = fmaxf(mx0, __shfl_xor_sync(0xffffffffu, mx0, 1));
        mx0 = fmaxf(mx0, __shfl_xor_sync(0xffffffffu, mx0, 2));
        mx1 = fmaxf(mx1, __shfl_xor_sync(0xffffffffu, mx1, 1));
        mx1 = fmaxf(mx1, __shfl_xor_sync(0xffffffffu, mx1, 2));

        const float al0 = __expf(m[0] - mx0);
        const float al1 = __expf(m[1] - mx1);
        m[0] = mx0; m[1] = mx1;
        #pragma unroll
        for (int nt = 0; nt < 8; nt++) {
            o[nt][0] *= al0; o[nt][1] *= al0;
            o[nt][2] *= al1; o[nt][3] *= al1;
        }

        uint32_t ph[4][4];
        float s0 = 0.f, s1 = 0.f;
        #pragma unroll
        for (int j = 0; j < 4; j++) {
            float e00 = __expf(sf[2*j][0]   - mx0);
            float e01 = __expf(sf[2*j][1]   - mx0);
            float e10 = __expf(sf[2*j][2]   - mx1);
            float e11 = __expf(sf[2*j][3]   - mx1);
            float e20 = __expf(sf[2*j+1][0] - mx0);
            float e21 = __expf(sf[2*j+1][1] - mx0);
            float e30 = __expf(sf[2*j+1][2] - mx1);
            float e31 = __expf(sf[2*j+1][3] - mx1);
            s0 += e00 + e01 + e20 + e21;
            s1 += e10 + e11 + e30 + e31;
            ph[j][0] = packh(e00, e01);
            ph[j][1] = packh(e10, e11);
            ph[j][2] = packh(e20, e21);
            ph[j][3] = packh(e30, e31);
        }
        s0 += __shfl_xor_sync(0xffffffffu, s0, 1);
        s0 += __shfl_xor_sync(0xffffffffu, s0, 2);
        s1 += __shfl_xor_sync(0xffffffffu, s1, 1);
        s1 += __shfl_xor_sync(0xffffffffu, s1, 2);
        l[0] = l[0]*al0 + s0;
        l[1] = l[1]*al1 + s1;

        #pragma unroll
        for (int j = 0; j < 4; j++) {
            #pragma unroll
            for (int p = 0; p < 4; p++) {
                uint32_t th[4];
                const uint32_t off = FSW((uint32_t)((j*16 + v_kv + b_row)*128
                                                     + p*32 + v_d*2));
                LDSM4T(th, stV + off);
                uint32_t b0[2] = { th[0], th[1] }, b1[2] = { th[2], th[3] };
                mma16816(o[2*p],   ph[j], b0);
                mma16816(o[2*p+1], ph[j], b1);
            }
        }
        __syncthreads();
    }

    const float inv0 = 1.f / l[0];
    const float inv1 = 1.f / l[1];
    const int row = b*Lc + qy + wq + g;
    #pragma unroll
    for (int nt = 0; nt < 8; nt++) {
        const int col = hcol + nt*8 + tg*2;
        *(uint32_t*)&O[(size_t)row * Dc + col]       = packh(o[nt][0]*inv0, o[nt][1]*inv0);
        *(uint32_t*)&O[(size_t)(row + 8) * Dc + col] = packh(o[nt][2]*inv1, o[nt][3]*inv1);
    }
}

// ---------------------------------------------------------------------------
// small kernels
// ---------------------------------------------------------------------------
__global__ __launch_bounds__(256) void cvt_f16(
    const float* __restrict__ x, __half* __restrict__ h)
{
    const size_t i = ((size_t)blockIdx.x * 256 + threadIdx.x) * 4;
    float4 v = *(const float4*)(x + i);
    *(uint32_t*)(h + i)     = packh(v.x, v.y);
    *(uint32_t*)(h + i + 2) = packh(v.z, v.w);
}

__global__ __launch_bounds__(256) void transpose_cvt(
    const float* __restrict__ W, __half* __restrict__ h,
    int K, int N, size_t ostrideZ)
{
    __shared__ float t[32][33];
    const size_t ibase = (size_t)blockIdx.z * K * N;
    const size_t obase = (size_t)blockIdx.z * ostrideZ;
    const int k0 = blockIdx.y * 32, n0 = blockIdx.x * 32;
    const int tx = threadIdx.x & 31, ty = threadIdx.x >> 5;
    #pragma unroll
    for (int r = 0; r < 32; r += 8)
        t[ty + r][tx] = W[ibase + (size_t)(k0 + ty + r) * N + n0 + tx];
    __syncthreads();
    #pragma unroll
    for (int r = 0; r < 32; r += 8) {
        const size_t o = obase + (size_t)(n0 + ty + r) * K + k0 + tx;
        h[o] = __float2half(t[tx][ty + r]);
    }
}

__global__ void bias_cat(const float* __restrict__ bq, const float* __restrict__ bk,
                         const float* __restrict__ bv, float* __restrict__ o)
{
    const int i = blockIdx.x, seg = blockIdx.y, j = threadIdx.x;
    const float* src = (seg == 0) ? bq : (seg == 1) ? bk : bv;
    o[i*QKVW + seg*1024 + j] = src[i*1024 + j];
}

__global__ __launch_bounds__(256) void add_ln(
    const float* __restrict__ x, const float* __restrict__ res,
    const float* __restrict__ g, const float* __restrict__ bta,
    float* __restrict__ y, __half* __restrict__ yh)
{
    __shared__ float rs[8], rq[8];
    const int tid = threadIdx.x;
    const size_t base = (size_t)blockIdx.x * 1024 + tid * 4;

    float4 a = *(const float4*)&x[base];
    if (res) {
        float4 r = *(const float4*)&res[base];
        a.x += r.x; a.y += r.y; a.z += r.z; a.w += r.w;
    }

    float s = a.x + a.y + a.z + a.w;
    float q = a.x*a.x + a.y*a.y + a.z*a.z + a.w*a.w;
    #pragma unroll
    for (int o = 16; o > 0; o >>= 1) {
        s += __shfl_xor_sync(0xffffffffu, s, o);
        q += __shfl_xor_sync(0xffffffffu, q, o);
    }
    if ((tid & 31) == 0) { rs[tid >> 5] = s; rq[tid >> 5] = q; }
    __syncthreads();
    s = 0.f; q = 0.f;
    #pragma unroll
    for (int i = 0; i < 8; i++) { s += rs[i]; q += rq[i]; }

    const float mean = s * (1.f / 1024.f);
    const float var  = q * (1.f / 1024.f) - mean * mean;
    const float rstd = rsqrtf(var + 1e-5f);

    const int c = tid * 4;
    float4 gv = *(const float4*)&g[c];
    float4 bv = *(const float4*)&bta[c];
    float4 o;
    o.x = (a.x - mean) * rstd * gv.x + bv.x;
    o.y = (a.y - mean) * rstd * gv.y + bv.y;
    o.z = (a.z - mean) * rstd * gv.z + bv.z;
    o.w = (a.w - mean) * rstd * gv.w + bv.w;
    if (y) *(float4*)&y[base] = o;

    *(uint32_t*)&yh[base]     = packh(o.x, o.y);
    *(uint32_t*)&yh[base + 2] = packh(o.z, o.w);
}

// ---------------------------------------------------------------------------
// Launch orchestration — round 9 DAG; BM128; residual-fused Wo; 2-stage flash
// ---------------------------------------------------------------------------
extern "C" void kernel_launch(void* const* d_in, const int* in_sizes, int n_in,
                              void* d_out, int out_size)
{
    const float* T    = (const float*)d_in[0];
    const float* A    = (const float*)d_in[1];
    const float* mask = (const float*)d_in[2];
    const int*   pad  = (const int*)  d_in[3];
    const float* Wq   = (const float*)d_in[4];
    const float* bq   = (const float*)d_in[5];
    const float* Wk   = (const float*)d_in[6];
    const float* bk   = (const float*)d_in[7];
    const float* Wv   = (const float*)d_in[8];
    const float* bv   = (const float*)d_in[9];
    const float* Wo   = (const float*)d_in[10];
    const float* ffW1 = (const float*)d_in[11];
    const float* ffb1 = (const float*)d_in[12];
    const float* ffW2 = (const float*)d_in[13];
    const float* ffb2 = (const float*)d_in[14];
    const float* lng  = (const float*)d_in[15];
    const float* lnb  = (const float*)d_in[16];
    float* out = (float*)d_out;

    static cudaStream_t sA = nullptr, sB = nullptr, sC = nullptr;
    static cudaEvent_t  eF = nullptr, eA = nullptr, eB = nullptr;
    static cudaEvent_t  eC = nullptr, eQ2 = nullptr, eKV2 = nullptr, eQ3 = nullptr;
    if (!sA) {
        cudaStreamCreateWithFlags(&sA, cudaStreamNonBlocking);
        cudaStreamCreateWithFlags(&sB, cudaStreamNonBlocking);
        cudaStreamCreateWithFlags(&sC, cudaStreamNonBlocking);
        cudaEventCreateWithFlags(&eF,  cudaEventDisableTiming);
        cudaEventCreateWithFlags(&eA,  cudaEventDisableTiming);
        cudaEventCreateWithFlags(&eB,  cudaEventDisableTiming);
        cudaEventCreateWithFlags(&eC,  cudaEventDisableTiming);
        cudaEventCreateWithFlags(&eQ2, cudaEventDisableTiming);
        cudaEventCreateWithFlags(&eKV2,cudaEventDisableTiming);
        cudaEventCreateWithFlags(&eQ3, cudaEventDisableTiming);
    }
    auto fork = [&]() {
        cudaEventRecord(eF, 0);
        cudaStreamWaitEvent(sA, eF, 0);
        cudaStreamWaitEvent(sB, eF, 0);
    };
    auto join = [&]() {
        cudaEventRecord(eA, sA);
        cudaEventRecord(eB, sB);
        cudaStreamWaitEvent(0, eA, 0);
        cudaStreamWaitEvent(0, eB, 0);
    };

    float *Mo0, *Mo1, *T1f, *A1f;
    cudaGetSymbolAddress((void**)&Mo0, g_Mo0);
    cudaGetSymbolAddress((void**)&Mo1, g_Mo1);
    cudaGetSymbolAddress((void**)&T1f, g_T1f);
    cudaGetSymbolAddress((void**)&A1f, g_A1f);

    __half *iT,*iA,*T1,*A1,*T2,*A2,*O0,*O1,*H0,*H1,*QKV0,*QKV1;
    __half *wc,*wo,*w1,*w2;
    float* bcat;
    cudaGetSymbolAddress((void**)&iT, g_iT);   cudaGetSymbolAddress((void**)&iA, g_iA);
    cudaGetSymbolAddress((void**)&T1, g_T1);   cudaGetSymbolAddress((void**)&A1, g_A1);
    cudaGetSymbolAddress((void**)&T2, g_T2);   cudaGetSymbolAddress((void**)&A2, g_A2);
    cudaGetSymbolAddress((void**)&O0, g_O0);   cudaGetSymbolAddress((void**)&O1, g_O1);
    cudaGetSymbolAddress((void**)&H0, g_H0);   cudaGetSymbolAddress((void**)&H1, g_H1);
    cudaGetSymbolAddress((void**)&QKV0, g_QKV0);
    cudaGetSymbolAddress((void**)&QKV1, g_QKV1);
    cudaGetSymbolAddress((void**)&wc, g_wc);   cudaGetSymbolAddress((void**)&wo, g_wo);
    cudaGetSymbolAddress((void**)&w1, g_w1);   cudaGetSymbolAddress((void**)&w2, g_w2);
    cudaGetSymbolAddress((void**)&bcat, g_bcat);

    cudaFuncSetAttribute(gemm_mma,   cudaFuncAttributeMaxDynamicSharedMemorySize, GEMM_SMEM);
    cudaFuncSetAttribute(flash_attn, cudaFuncAttributeMaxDynamicSharedMemorySize, FA_SMEM);

    const size_t DD = (size_t)Dc * Dc;
    const size_t WCZ = (size_t)QKVW * Dc;

    auto gemm = [&](cudaStream_t st, const __half* a, const __half* b,
                    const float* bias, const float* resid, float* c, __half* ch,
                    int M, int N, int K, int ldc, int coff, int relu) {
        gemm_mma<<<dim3(N/128, M/128), 256, GEMM_SMEM, st>>>(
            a, b, bias, resid, c, ch, M, N, K, ldc, coff, relu);
    };

    // ------- Phase 0: CRITICAL prep (sA/sB) + DEFERRED prep (sC) -------
    fork();
    cudaStreamWaitEvent(sC, eF, 0);
    transpose_cvt<<<dim3(32,32,2), 256, 0, sA>>>(Wq, wc,        Dc, Dc, WCZ);
    transpose_cvt<<<dim3(32,32,2), 256, 0, sA>>>(Wk, wc + DD,   Dc, Dc, WCZ);
    transpose_cvt<<<dim3(32,32,2), 256, 0, sA>>>(Wv, wc + 2*DD, Dc, Dc, WCZ);
    bias_cat<<<dim3(4,3), 1024, 0, sA>>>(bq, bk, bv, bcat);
    cvt_f16<<<BLc, 256, 0, sA>>>(T, iT);
    transpose_cvt<<<dim3(32,32,2), 256, 0, sB>>>(Wo, wo, Dc, Dc, DD);
    cvt_f16<<<BLc, 256, 0, sB>>>(A, iA);
    transpose_cvt<<<dim3(32,32,2), 256, 0, sC>>>(Wq + 2*DD, wc + 2*WCZ,        Dc, Dc, WCZ);
    transpose_cvt<<<dim3(32,32,2), 256, 0, sC>>>(Wk + 2*DD, wc + 2*WCZ + DD,   Dc, Dc, WCZ);
    transpose_cvt<<<dim3(32,32,2), 256, 0, sC>>>(Wv + 2*DD, wc + 2*WCZ + 2*DD, Dc, Dc, WCZ);
    transpose_cvt<<<dim3(32,32,2), 256, 0, sC>>>(Wo + 2*DD, wo + 2*DD, Dc, Dc, DD);
    transpose_cvt<<<dim3(128,32,2), 256, 0, sC>>>(ffW1, w1, Dc, Fc, (size_t)Dc*Fc);
    transpose_cvt<<<dim3(32,128,2), 256, 0, sC>>>(ffW2, w2, Fc, Dc, (size_t)Fc*Dc);
    cudaEventRecord(eC, sC);
    join();

    // ---------------- Phase 1: mha0 (T, sA) || mha1 (A, sB) ----------------
    fork();
    gemm(sA, iT, wc, bcat, nullptr, nullptr, QKV0, BLc, QKVW, Dc, QKVW, 0, 0);
    flash_attn<<<dim3(Lc/128, 64), 256, FA_SMEM, sA>>>(QKV0, mask, pad, O0);
    gemm(sA, O0, wo, nullptr, T, Mo0, nullptr, BLc, Dc, Dc, Dc, 0, 0);   // Mo0 = O0@Wo + T
    add_ln<<<BLc, 256, 0, sA>>>(Mo0, nullptr, lng, lnb, T1f, T1);
    gemm(sB, iA, wc + WCZ, bcat + QKVW, nullptr, nullptr, QKV1, BLc, QKVW, Dc, QKVW, 0, 0);
    flash_attn<<<dim3(Lc/128, 64), 256, FA_SMEM, sB>>>(QKV1, mask, pad, O1);
    gemm(sB, O1, wo + DD, nullptr, A, Mo1, nullptr, BLc, Dc, Dc, Dc, 0, 0);
    add_ln<<<BLc, 256, 0, sB>>>(Mo1, nullptr, lng + Dc, lnb + Dc, A1f, A1);
    join();
    cudaStreamWaitEvent(0, eC, 0);

    // ------- Phase 2: KV2 (sA) || Q2,Q3 (sB); flash2 waits only {KV2,Q2} -------
    fork();
    gemm(sA, A1, wc + 2*WCZ + DD, bcat + 2*QKVW + 1024, nullptr,
         nullptr, QKV0, BLc, 2*Dc, Dc, QKVW, 1024, 0);
    cudaEventRecord(eKV2, sA);
    gemm(sB, T1, wc + 2*WCZ, bcat + 2*QKVW, nullptr, nullptr, QKV0,
         BLc, Dc, Dc, QKVW, 0, 0);
    cudaEventRecord(eQ2, sB);
    gemm(sB, A1, wc + 3*WCZ, bcat + 3*QKVW, nullptr, nullptr, QKV1,
         BLc, Dc, Dc, QKVW, 0, 0);
    cudaEventRecord(eQ3, sB);

    cudaStreamWaitEvent(0, eKV2, 0);
    cudaStreamWaitEvent(0, eQ2, 0);
    flash_attn<<<dim3(Lc/128, 64), 256, FA_SMEM>>>(QKV0, mask, pad, O0);
    gemm(0, O0, wo + 2*DD, nullptr, T1f, Mo0, nullptr, BLc, Dc, Dc, Dc, 0, 0);
    add_ln<<<BLc, 256>>>(Mo0, nullptr, lng + 2*Dc, lnb + 2*Dc, nullptr, T2);

    // ------- Phase 3: mha3 chain + FFN-A (sA)  ||  FFN-T (sB) -------
    fork();
    gemm(sA, T2, wc + 3*WCZ + DD, bcat + 3*QKVW + 1024, nullptr,
         nullptr, QKV1, BLc, 2*Dc, Dc, QKVW, 1024, 0);
    cudaStreamWaitEvent(sA, eQ3, 0);
    flash_attn<<<dim3(Lc/128, 64), 256, FA_SMEM, sA>>>(QKV1, mask, pad, O0);
    gemm(sA, O0, wo + 3*DD, nullptr, A1f, Mo0, nullptr, BLc, Dc, Dc, Dc, 0, 0);
    add_ln<<<BLc, 256, 0, sA>>>(Mo0, nullptr, lng + 3*Dc, lnb + 3*Dc, nullptr, A2);
    gemm(sA, A2, w1 + (size_t)Dc*Fc, ffb1 + Fc, nullptr, nullptr, H1,
         BLc, Fc, Dc, Fc, 0, 1);
    gemm(sA, H1, w2 + (size_t)Fc*Dc, ffb2 + Dc, nullptr,
         out + (size_t)BLc*Dc, nullptr, BLc, Dc, Fc, Dc, 0, 0);
    gemm(sB, T2, w1, ffb1, nullptr, nullptr, H0, BLc, Fc, Dc, Fc, 0, 1);
    gemm(sB, H0, w2, ffb2, nullptr, out, nullptr, BLc, Dc, Fc, Dc, 0, 0);
    join();
}